// round 12
// baseline (speedup 1.0000x reference)
#include <cuda_runtime.h>
#include <cuda_bf16.h>
#include <cuda_fp16.h>

typedef unsigned int u32;
typedef unsigned long long u64;

#define Bn 4
#define Sn 512
#define Hn 768
#define NHn 12
#define Fn 3072
#define Ln 6
#define MR (Bn*Sn)          // 2048
#define QKVN 2304
#define BH (Bn*NHn)         // 48

// ---------------- scratch (device globals) ----------------
__device__ __half g_wqkv16[(size_t)Ln*QKVN*Hn];
__device__ __half g_wo16[(size_t)Ln*Hn*Hn];
__device__ __half g_w116[(size_t)Ln*Hn*Fn];
__device__ __half g_w216[(size_t)Ln*Fn*Hn];
__device__ float g_x[MR*Hn];
__device__ float g_y[2*MR*Hn];                 // split-K partials (fp32)
__device__ float g_bqkv[Ln*QKVN];
__device__ __half g_xf[MR*Hn];
__device__ __half g_qkv16[(size_t)MR*QKVN];
__device__ __half g_ct16[MR*Hn];
__device__ __half g_f16[(size_t)MR*Fn];

// ---------------- helpers ----------------
__device__ __forceinline__ u32 s2u(const void* p) {
    u32 a;
    asm("{ .reg .u64 t; cvta.to.shared.u64 t, %1; cvt.u32.u64 %0, t; }" : "=r"(a) : "l"(p));
    return a;
}
__device__ __forceinline__ u32 swz(u32 o) { return o ^ ((o >> 3) & 0x70); }

__device__ __forceinline__ void cpasync16(u32 dst, const void* src) {
    asm volatile("cp.async.cg.shared.global [%0], [%1], 16;" :: "r"(dst), "l"(src) : "memory");
}
__device__ __forceinline__ void ldsm4(u32& r0, u32& r1, u32& r2, u32& r3, u32 a) {
    asm volatile("ldmatrix.sync.aligned.m8n8.x4.shared.b16 {%0,%1,%2,%3}, [%4];"
                 : "=r"(r0), "=r"(r1), "=r"(r2), "=r"(r3) : "r"(a));
}
__device__ __forceinline__ void ldsm4t(u32& r0, u32& r1, u32& r2, u32& r3, u32 a) {
    asm volatile("ldmatrix.sync.aligned.m8n8.x4.trans.shared.b16 {%0,%1,%2,%3}, [%4];"
                 : "=r"(r0), "=r"(r1), "=r"(r2), "=r"(r3) : "r"(a));
}
__device__ __forceinline__ void mma16816h(float* c, const u32* a, const u32* b) {
    asm volatile("mma.sync.aligned.m16n8k16.row.col.f32.f16.f16.f32 "
                 "{%0,%1,%2,%3}, {%4,%5,%6,%7}, {%8,%9}, {%0,%1,%2,%3};"
                 : "+f"(c[0]), "+f"(c[1]), "+f"(c[2]), "+f"(c[3])
                 : "r"(a[0]), "r"(a[1]), "r"(a[2]), "r"(a[3]), "r"(b[0]), "r"(b[1]));
}
// fp16 accumulator variant
__device__ __forceinline__ void mma16816hh(u32* c, const u32* a, const u32* b) {
    asm volatile("mma.sync.aligned.m16n8k16.row.col.f16.f16.f16.f16 "
                 "{%0,%1}, {%2,%3,%4,%5}, {%6,%7}, {%0,%1};"
                 : "+r"(c[0]), "+r"(c[1])
                 : "r"(a[0]), "r"(a[1]), "r"(a[2]), "r"(a[3]), "r"(b[0]), "r"(b[1]));
}
__device__ __forceinline__ u32 packh2(float v0, float v1) {
    __half2 h = __floats2half2_rn(v0, v1);
    return *reinterpret_cast<u32*>(&h);
}

// ==================================================================
// fp16 single-pass GEMM. MT x NT, BK=64, 512 threads (16 warps 4x4).
// EPI: 0=bias->fp16  4=bias+relu->fp16  5=split-K raw partial -> fp32
// HACC: 1 = fp16 accumulators in the MMA chain, promoted to fp32 per slab
// ==================================================================
template<int MT, int NT, int EPI, int HACC>
__global__ void __launch_bounds__(512)
gemm1(const __half* __restrict__ A, int lda, const __half* __restrict__ B, int ldb,
      float* __restrict__ Cf, __half* __restrict__ Ch, int ldc,
      const float* __restrict__ bias, int K)
{
    constexpr int WM = MT / 4, WN = NT / 4;
    constexpr int MI = WM / 16, NI = WN / 8;
    constexpr u32 ASZ = (u32)MT * 128u, BSZ = (u32)NT * 128u;
    constexpr u32 STG = ASZ + BSZ;

    if (EPI == 5) {
        A += (size_t)blockIdx.z * (u32)(K >> 1);
        B += (size_t)blockIdx.z * (u32)(K >> 1);
        K >>= 1;
    }

    extern __shared__ char smem[];
    const u32 sb = s2u(smem);
    const int tid = threadIdx.x, wid = tid >> 5, lane = tid & 31;
    const int warp_m = wid >> 2, warp_n = wid & 3;
    const int m0 = blockIdx.y * MT, n0 = blockIdx.x * NT;
    const int nsl = K >> 6;

    float acc[MI][NI][4];
#pragma unroll
    for (int mi = 0; mi < MI; mi++)
#pragma unroll
        for (int ni = 0; ni < NI; ni++)
#pragma unroll
            for (int q = 0; q < 4; q++) acc[mi][ni][q] = 0.f;

    auto prefetch = [&](int sl) {
        const u32 base = sb + (u32)(sl % 3) * STG;
#pragma unroll
        for (int i = 0; i < MT * 8 / 512; i++) {
            int u = tid + i * 512;
            int r = u >> 3, c = u & 7;
            cpasync16(base + swz((u32)(r * 128 + c * 16)),
                      A + (size_t)(m0 + r) * lda + sl * 64 + c * 8);
        }
#pragma unroll
        for (int i = 0; i < NT * 8 / 512; i++) {
            int u = tid + i * 512;
            int r = u >> 3, c = u & 7;
            cpasync16(base + ASZ + swz((u32)(r * 128 + c * 16)),
                      B + (size_t)(n0 + r) * ldb + sl * 64 + c * 8);
        }
        asm volatile("cp.async.commit_group;" ::: "memory");
    };

    prefetch(0); prefetch(1);

    for (int it = 0; it < nsl; it++) {
        if (it < nsl - 1) asm volatile("cp.async.wait_group 1;" ::: "memory");
        else              asm volatile("cp.async.wait_group 0;" ::: "memory");
        __syncthreads();
        if (it + 2 < nsl) prefetch(it + 2);

        const u32 ab = sb + (u32)(it % 3) * STG;
        const u32 bb = ab + ASZ;

        u32 hacc[MI][NI][2];
        if (HACC) {
#pragma unroll
            for (int mi = 0; mi < MI; mi++)
#pragma unroll
                for (int ni = 0; ni < NI; ni++) { hacc[mi][ni][0] = 0u; hacc[mi][ni][1] = 0u; }
        }

#pragma unroll
        for (int ks = 0; ks < 4; ks++) {
            u32 ar[MI][4];
#pragma unroll
            for (int mi = 0; mi < MI; mi++) {
                int row = warp_m * WM + mi * 16 + (lane & 15);
                u32 off = swz((u32)(row * 128 + (ks * 16 + (lane >> 4) * 8) * 2));
                ldsm4(ar[mi][0], ar[mi][1], ar[mi][2], ar[mi][3], ab + off);
            }
            u32 br[NI][2];
#pragma unroll
            for (int nj = 0; nj < NI / 2; nj++) {
                int nrow = warp_n * WN + nj * 16 + (lane & 7) + ((lane >> 4) << 3);
                u32 off = swz((u32)(nrow * 128 + (ks * 16 + ((lane >> 3) & 1) * 8) * 2));
                u32 r0, r1, r2, r3;
                ldsm4(r0, r1, r2, r3, bb + off);
                br[2 * nj][0] = r0; br[2 * nj][1] = r1;
                br[2 * nj + 1][0] = r2; br[2 * nj + 1][1] = r3;
            }
#pragma unroll
            for (int mi = 0; mi < MI; mi++)
#pragma unroll
                for (int ni = 0; ni < NI; ni++) {
                    if (HACC) mma16816hh(hacc[mi][ni], ar[mi], br[ni]);
                    else      mma16816h(acc[mi][ni], ar[mi], br[ni]);
                }
        }

        if (HACC) {   // promote slab partial to fp32
#pragma unroll
            for (int mi = 0; mi < MI; mi++)
#pragma unroll
                for (int ni = 0; ni < NI; ni++) {
                    float2 lo = __half22float2(*(__half2*)&hacc[mi][ni][0]);
                    float2 hi = __half22float2(*(__half2*)&hacc[mi][ni][1]);
                    acc[mi][ni][0] += lo.x; acc[mi][ni][1] += lo.y;
                    acc[mi][ni][2] += hi.x; acc[mi][ni][3] += hi.y;
                }
        }
    }

    const int tg = lane & 3, g = lane >> 2;
    const size_t zoff = (EPI == 5) ? (size_t)blockIdx.z * MR * ldc : 0;
#pragma unroll
    for (int mi = 0; mi < MI; mi++)
#pragma unroll
        for (int half = 0; half < 2; half++) {
            const int mrow = m0 + warp_m * WM + mi * 16 + half * 8 + g;
#pragma unroll
            for (int ni = 0; ni < NI; ni++) {
                const int col = n0 + warp_n * WN + ni * 8 + tg * 2;
                float v0 = acc[mi][ni][half * 2];
                float v1 = acc[mi][ni][half * 2 + 1];
                size_t off = (size_t)mrow * ldc + col;
                if (EPI == 5) {
                    *(float2*)(Cf + zoff + off) = make_float2(v0, v1);
                } else {
                    v0 += bias[col]; v1 += bias[col + 1];
                    if (EPI == 4) { v0 = fmaxf(v0, 0.f); v1 = fmaxf(v1, 0.f); }
                    *(u32*)(Ch + off) = packh2(v0, v1);
                }
            }
        }
}

// ==================================================================
// Fused attention (all fp16): scores + softmax + P@V. 64 q-rows/(b,h).
// smem: Q[0,8K)  K[8K,72K)->P  V[72K,136K)  red[136K..]
// ==================================================================
#define ATT_KP   8192u
#define ATT_V    73728u
#define ATT_RED  139264
#define SMEM_ATT (ATT_RED + 2048)

__global__ void __launch_bounds__(256)
attn_fused(const __half* __restrict__ qkv, const int* __restrict__ tok,
           float* __restrict__ attn, __half* __restrict__ ct)
{
    extern __shared__ char smem[];
    const u32 sb = s2u(smem);
    const int tid = threadIdx.x, wid = tid >> 5, lane = tid & 31;
    const int g = lane >> 2, tg = lane & 3;
    const int m0 = blockIdx.x * 64;
    const int zbh = blockIdx.y;
    const int b = zbh / NHn, h = zbh - b * NHn;

    const __half* Q_src = qkv + (size_t)(b * Sn + m0) * QKVN + h * 64;
    const __half* K_src = qkv + (size_t)(b * Sn) * QKVN + 768 + h * 64;
    const __half* V_src = qkv + (size_t)(b * Sn) * QKVN + 1536 + h * 64;

    for (int u = tid; u < 512; u += 256) {
        int r = u >> 3, c = u & 7;
        cpasync16(sb + swz((u32)(r * 128 + c * 16)), Q_src + (size_t)r * QKVN + c * 8);
    }
    for (int u = tid; u < 4096; u += 256) {
        int r = u >> 3, c = u & 7;
        cpasync16(sb + ATT_KP + swz((u32)(r * 128 + c * 16)), K_src + (size_t)r * QKVN + c * 8);
    }
    asm volatile("cp.async.commit_group;" ::: "memory");
    for (int u = tid; u < 4096; u += 256) {
        int r = u >> 3, c = u & 7;
        cpasync16(sb + ATT_V + swz((u32)(r * 128 + c * 16)), V_src + (size_t)r * QKVN + c * 8);
    }
    asm volatile("cp.async.commit_group;" ::: "memory");

    asm volatile("cp.async.wait_group 1;" ::: "memory");
    __syncthreads();

    // ---- scores = Q K^T ----
    float acc[4][8][4];
#pragma unroll
    for (int mi = 0; mi < 4; mi++)
#pragma unroll
        for (int ni = 0; ni < 8; ni++)
#pragma unroll
            for (int q = 0; q < 4; q++) acc[mi][ni][q] = 0.f;

#pragma unroll
    for (int ks = 0; ks < 4; ks++) {
        u32 arg[4][4];
#pragma unroll
        for (int mi = 0; mi < 4; mi++) {
            int row = mi * 16 + (lane & 15);
            u32 off = swz((u32)(row * 128 + (ks * 16 + (lane >> 4) * 8) * 2));
            ldsm4(arg[mi][0], arg[mi][1], arg[mi][2], arg[mi][3], sb + off);
        }
        u32 brg[8][2];
#pragma unroll
        for (int nj = 0; nj < 4; nj++) {
            int nrow = wid * 64 + nj * 16 + (lane & 7) + ((lane >> 4) << 3);
            u32 off = swz((u32)(nrow * 128 + (ks * 16 + ((lane >> 3) & 1) * 8) * 2));
            u32 r0, r1, r2, r3;
            ldsm4(r0, r1, r2, r3, sb + ATT_KP + off);
            brg[2 * nj][0] = r0; brg[2 * nj][1] = r1;
            brg[2 * nj + 1][0] = r2; brg[2 * nj + 1][1] = r3;
        }
#pragma unroll
        for (int mi = 0; mi < 4; mi++)
#pragma unroll
            for (int ni = 0; ni < 8; ni++)
                mma16816h(acc[mi][ni], arg[mi], brg[ni]);
    }
    __syncthreads();

    // ---- scale + mask + exp (no max-sub; logits small, mask underflows) ----
    float mk[8][2];
#pragma unroll
    for (int ni = 0; ni < 8; ni++) {
        int c = wid * 64 + ni * 8 + tg * 2;
        mk[ni][0] = (tok[b * Sn + c]     == 0) ? -10000.f : 0.f;
        mk[ni][1] = (tok[b * Sn + c + 1] == 0) ? -10000.f : 0.f;
    }

    float* red = (float*)(smem + ATT_RED);
    float rsum[8];

#pragma unroll
    for (int mi = 0; mi < 4; mi++)
#pragma unroll
        for (int half = 0; half < 2; half++) {
            float s = 0.f;
#pragma unroll
            for (int ni = 0; ni < 8; ni++) {
                float e0 = __expf(acc[mi][ni][half * 2]     * 0.125f + mk[ni][0]);
                float e1 = __expf(acc[mi][ni][half * 2 + 1] * 0.125f + mk[ni][1]);
                acc[mi][ni][half * 2] = e0; acc[mi][ni][half * 2 + 1] = e1;
                s += e0 + e1;
            }
            s += __shfl_xor_sync(0xffffffffu, s, 1);
            s += __shfl_xor_sync(0xffffffffu, s, 2);
            int row = mi * 16 + half * 8 + g;
            if (tg == 0) red[row * 8 + wid] = s;
        }
    __syncthreads();
#pragma unroll
    for (int mi = 0; mi < 4; mi++)
#pragma unroll
        for (int half = 0; half < 2; half++) {
            int row = mi * 16 + half * 8 + g;
            float s = 0.f;
#pragma unroll
            for (int w = 0; w < 8; w++) s += red[row * 8 + w];
            rsum[mi * 2 + half] = 1.f / s;
        }

    // ---- normalize in regs; store P fp16 to smem ----
#pragma unroll
    for (int mi = 0; mi < 4; mi++)
#pragma unroll
        for (int half = 0; half < 2; half++) {
            int row = mi * 16 + half * 8 + g;
            float inv = rsum[mi * 2 + half];
#pragma unroll
            for (int ni = 0; ni < 8; ni++) {
                int col = ni * 8 + tg * 2;
                float p0 = acc[mi][ni][half * 2]     * inv;
                float p1 = acc[mi][ni][half * 2 + 1] * inv;
                acc[mi][ni][half * 2] = p0; acc[mi][ni][half * 2 + 1] = p1;
                u32 off = (u32)(wid * 8192) + swz((u32)(row * 128 + col * 2));
                *(u32*)(smem + ATT_KP + off) = packh2(p0, p1);
            }
        }

    asm volatile("cp.async.wait_group 0;" ::: "memory");
    __syncthreads();

    // ---- ctx = P @ V, attn fp32 stores interleaved per slab ----
    const int wm = wid >> 2, wn = wid & 3;
    float acc2[2][2][4];
#pragma unroll
    for (int mi = 0; mi < 2; mi++)
#pragma unroll
        for (int ni = 0; ni < 2; ni++)
#pragma unroll
            for (int q = 0; q < 4; q++) acc2[mi][ni][q] = 0.f;

#pragma unroll
    for (int sl = 0; sl < 8; sl++) {
        {
            const int smi = sl >> 1, shalf = sl & 1;
            int row = smi * 16 + shalf * 8 + g;
            size_t rbase = (size_t)zbh * Sn * Sn + (size_t)(m0 + row) * Sn + wid * 64;
#pragma unroll
            for (int ni = 0; ni < 8; ni++) {
                int col = ni * 8 + tg * 2;
                *(float2*)(attn + rbase + col) =
                    make_float2(acc[smi][ni][shalf * 2], acc[smi][ni][shalf * 2 + 1]);
            }
        }
#pragma unroll
        for (int ks = 0; ks < 4; ks++) {
            u32 ar[2][4];
#pragma unroll
            for (int mi = 0; mi < 2; mi++) {
                int row = wm * 32 + mi * 16 + (lane & 15);
                u32 aoff = (u32)(sl * 8192) + swz((u32)(row * 128 + (ks * 16 + (lane >> 4) * 8) * 2));
                ldsm4(ar[mi][0], ar[mi][1], ar[mi][2], ar[mi][3], sb + ATT_KP + aoff);
            }
            int srow = sl * 64 + ks * 16 + (lane & 7) + ((lane >> 3) & 1) * 8;
            int dcol = wn * 16 + ((lane >> 4) << 3);
            u32 boff = swz((u32)(srow * 128 + dcol * 2));
            u32 br[2][2], r0, r1, r2, r3;
            ldsm4t(r0, r1, r2, r3, sb + ATT_V + boff);
            br[0][0] = r0; br[0][1] = r1; br[1][0] = r2; br[1][1] = r3;
#pragma unroll
            for (int mi = 0; mi < 2; mi++)
#pragma unroll
                for (int ni = 0; ni < 2; ni++)
                    mma16816h(acc2[mi][ni], ar[mi], br[ni]);
        }
    }

#pragma unroll
    for (int mi = 0; mi < 2; mi++)
#pragma unroll
        for (int half = 0; half < 2; half++) {
            int row = m0 + wm * 32 + mi * 16 + half * 8 + g;
#pragma unroll
            for (int ni = 0; ni < 2; ni++) {
                int col = wn * 16 + ni * 8 + tg * 2;
                size_t off = (size_t)(b * Sn + row) * Hn + h * 64 + col;
                *(u32*)(ct + off) = packh2(acc2[mi][ni][half * 2], acc2[mi][ni][half * 2 + 1]);
            }
        }
}

// ==================================================================
// weight convert+transpose: fp32 [K,N] -> fp16 [N,K]
// ==================================================================
__global__ void __launch_bounds__(256)
wconv(const float* __restrict__ src0, __half* __restrict__ dst0,
      int K, int N, long in_l, long out_l)
{
    __shared__ float t[32][132];
    const float* src = src0 + (size_t)blockIdx.z * in_l;
    __half* dst = dst0 + (size_t)blockIdx.z * out_l;
    const int n0 = blockIdx.x * 128, k0 = blockIdx.y * 32;
    const int tid = threadIdx.x;

#pragma unroll
    for (int i = 0; i < 4; i++) {
        int idx = tid + i * 256;
        int r = idx >> 5, c = (idx & 31) << 2;
        float4 v = *(const float4*)(src + (size_t)(k0 + r) * N + n0 + c);
        t[r][c] = v.x; t[r][c + 1] = v.y; t[r][c + 2] = v.z; t[r][c + 3] = v.w;
    }
    __syncthreads();
#pragma unroll
    for (int i = 0; i < 4; i++) {
        int idx = tid + i * 256;
        int n = idx >> 3, ks = (idx & 7) << 2;
        u32 p0 = packh2(t[ks][n],     t[ks + 1][n]);
        u32 p1 = packh2(t[ks + 2][n], t[ks + 3][n]);
        size_t off = (size_t)(n0 + n) * K + k0 + ks;
        *(u32*)(dst + off)     = p0;
        *(u32*)(dst + off + 2) = p1;
    }
}

__global__ void __launch_bounds__(256)
wconv4(const float* __restrict__ wq, const float* __restrict__ wk,
       const float* __restrict__ wv, const float* __restrict__ wo,
       __half* __restrict__ oqkv, __half* __restrict__ owo, int zoff)
{
    __shared__ float t[32][132];
    int z = blockIdx.z + zoff, l = z >> 2, which = z & 3;
    const float* src = (which == 0 ? wq : which == 1 ? wk : which == 2 ? wv : wo)
                       + (size_t)l * Hn * Hn;
    __half* dst;
    size_t obase;
    if (which < 3) { dst = oqkv; obase = (size_t)l * QKVN * Hn + (size_t)which * 768 * Hn; }
    else           { dst = owo;  obase = (size_t)l * Hn * Hn; }
    const int n0 = blockIdx.x * 128, k0 = blockIdx.y * 32;
    const int tid = threadIdx.x;

#pragma unroll
    for (int i = 0; i < 4; i++) {
        int idx = tid + i * 256;
        int r = idx >> 5, c = (idx & 31) << 2;
        float4 v = *(const float4*)(src + (size_t)(k0 + r) * Hn + n0 + c);
        t[r][c] = v.x; t[r][c + 1] = v.y; t[r][c + 2] = v.z; t[r][c + 3] = v.w;
    }
    __syncthreads();
#pragma unroll
    for (int i = 0; i < 4; i++) {
        int idx = tid + i * 256;
        int n = idx >> 3, ks = (idx & 7) << 2;
        u32 p0 = packh2(t[ks][n],     t[ks + 1][n]);
        u32 p1 = packh2(t[ks + 2][n], t[ks + 3][n]);
        size_t off = obase + (size_t)(n0 + n) * Hn + k0 + ks;
        *(u32*)(dst + off)     = p0;
        *(u32*)(dst + off + 2) = p1;
    }
}

__global__ void embed_bias(const int* __restrict__ tok, const float* __restrict__ emb,
                           const float* __restrict__ pos, float* __restrict__ x,
                           __half* __restrict__ xf,
                           const float* __restrict__ bq, const float* __restrict__ bk,
                           const float* __restrict__ bv, float* __restrict__ obias) {
    if (blockIdx.x < MR) {
        int row = blockIdx.x;
        int t = tok[row];
        const float* e = emb + (size_t)t * Hn;
        const float* p = pos + (size_t)(row % Sn) * Hn;
        size_t base = (size_t)row * Hn;
        for (int c = threadIdx.x; c < Hn; c += blockDim.x) {
            float v = e[c] + p[c];
            x[base + c] = v;
            xf[base + c] = __float2half(v);
        }
    } else {
        int i = (blockIdx.x - MR) * 256 + threadIdx.x;
        if (i < Ln * QKVN) {
            int l = i / QKVN, n = i - l * QKVN;
            float v = (n < 768) ? bq[l * Hn + n]
                    : (n < 1536) ? bk[l * Hn + n - 768] : bv[l * Hn + n - 1536];
            obias[i] = v;
        }
    }
}

// ==================================================================
// warp-per-row layernorm over (y0 + y1 + bias + resid), fp32 partials
// ==================================================================
__global__ void __launch_bounds__(256)
layernorm_sum(const float* __restrict__ y0, const float* __restrict__ y1,
              const float* __restrict__ bias, const float* __restrict__ resid,
              const float* __restrict__ g, const float* __restrict__ be,
              float* __restrict__ out, __half* __restrict__ of) {
    const int row = blockIdx.x * 8 + (threadIdx.x >> 5);
    const int lane = threadIdx.x & 31;
    const size_t rb = (size_t)row * Hn;

    float4 v[6];
    float s = 0.f, sq = 0.f;
#pragma unroll
    for (int i = 0; i < 6; i++) {
        int idx = i * 128 + lane * 4;
        float4 a0 = *(const float4*)(y0 + rb + idx);
        float4 a1 = *(const float4*)(y1 + rb + idx);
        float4 bv = *(const float4*)(bias + idx);
        float4 rv = *(const float4*)(resid + rb + idx);
        v[i].x = a0.x + a1.x + bv.x + rv.x;
        v[i].y = a0.y + a1.y + bv.y + rv.y;
        v[i].z = a0.z + a1.z + bv.z + rv.z;
        v[i].w = a0.w + a1.w + bv.w + rv.w;
        s  += v[i].x + v[i].y + v[i].z + v[i].w;
        sq += v[i].x * v[i].x + v[i].y * v[i].y + v[i].z * v[i].z + v[i].w * v[i].w;
    }
#pragma unroll
    for (int o = 16; o; o >>= 1) {
        s  += __shfl_xor_sync(0xffffffffu, s, o);
        sq += __shfl_xor_sync(0xffffffffu, sq, o);
    }
    float m = s * (1.0f / Hn);
    float var = sq * (1.0f / Hn) - m * m;
    float inv = rsqrtf(var + 1e-12f);

#pragma unroll
    for (int i = 0; i < 6; i++) {
        int idx = i * 128 + lane * 4;
        float4 gg = *(const float4*)(g + idx);
        float4 bb = *(const float4*)(be + idx);
        float4 r;
        r.x = (v[i].x - m) * inv * gg.x + bb.x;
        r.y = (v[i].y - m) * inv * gg.y + bb.y;
        r.z = (v[i].z - m) * inv * gg.z + bb.z;
        r.w = (v[i].w - m) * inv * gg.w + bb.w;
        *(float4*)(out + rb + idx) = r;
        u32 h0 = packh2(r.x, r.y), h1 = packh2(r.z, r.w);
        *(u32*)(of + rb + idx)     = h0;
        *(u32*)(of + rb + idx + 2) = h1;
    }
}

// ==================================================================
#define SMEM_G1B (3 * (128*128 + 128*128))       // 98304 (128x128)
#define SMEM_G1A (3 * (64*128  + 128*128))       // 73728 (64x128)

extern "C" void kernel_launch(void* const* d_in, const int* in_sizes, int n_in,
                              void* d_out, int out_size) {
    const int*   tok = (const int*)d_in[0];
    const float* emb = (const float*)d_in[1];
    const float* pos = (const float*)d_in[2];
    const float* wq  = (const float*)d_in[3];
    const float* bq  = (const float*)d_in[4];
    const float* wk  = (const float*)d_in[5];
    const float* bk  = (const float*)d_in[6];
    const float* wv  = (const float*)d_in[7];
    const float* bv  = (const float*)d_in[8];
    const float* wo  = (const float*)d_in[9];
    const float* bo  = (const float*)d_in[10];
    const float* g1  = (const float*)d_in[11];
    const float* be1 = (const float*)d_in[12];
    const float* w1  = (const float*)d_in[13];
    const float* b1  = (const float*)d_in[14];
    const float* w2  = (const float*)d_in[15];
    const float* b2  = (const float*)d_in[16];
    const float* g2  = (const float*)d_in[17];
    const float* be2 = (const float*)d_in[18];

    float* out      = (float*)d_out;
    float* attn_out = out + (size_t)MR * Hn;

    float *x, *y, *bqkv;
    __half *wqkv16, *wo16, *w116, *w216, *xf, *qkv16, *ct, *f16;
    cudaGetSymbolAddress((void**)&x, g_x);
    cudaGetSymbolAddress((void**)&y, g_y);
    cudaGetSymbolAddress((void**)&bqkv, g_bqkv);
    cudaGetSymbolAddress((void**)&wqkv16, g_wqkv16);
    cudaGetSymbolAddress((void**)&wo16, g_wo16);
    cudaGetSymbolAddress((void**)&w116, g_w116);
    cudaGetSymbolAddress((void**)&w216, g_w216);
    cudaGetSymbolAddress((void**)&xf, g_xf);
    cudaGetSymbolAddress((void**)&qkv16, g_qkv16);
    cudaGetSymbolAddress((void**)&ct, g_ct16);
    cudaGetSymbolAddress((void**)&f16, g_f16);

    cudaFuncSetAttribute(gemm1<128,128,0,0>, cudaFuncAttributeMaxDynamicSharedMemorySize, SMEM_G1B);
    cudaFuncSetAttribute(gemm1<64,128,5,0>,  cudaFuncAttributeMaxDynamicSharedMemorySize, SMEM_G1A);
    cudaFuncSetAttribute(gemm1<128,128,4,1>, cudaFuncAttributeMaxDynamicSharedMemorySize, SMEM_G1B);
    cudaFuncSetAttribute(attn_fused, cudaFuncAttributeMaxDynamicSharedMemorySize, SMEM_ATT);

    static cudaStream_t s2 = nullptr;
    static cudaEvent_t ev1 = nullptr, ev2 = nullptr;
    if (!s2) {
        cudaStreamCreateWithFlags(&s2, cudaStreamNonBlocking);
        cudaEventCreateWithFlags(&ev1, cudaEventDisableTiming);
        cudaEventCreateWithFlags(&ev2, cudaEventDisableTiming);
    }

    // ---- prologue: layer-0 weights on main stream ----
    wconv4<<<dim3(Hn/128, Hn/32, 4), 256>>>(wq, wk, wv, wo, wqkv16, wo16, 0);
    wconv<<<dim3(Fn/128, Hn/32, 1), 256>>>(w1, w116, Hn, Fn, (long)Hn*Fn, (long)Hn*Fn);
    wconv<<<dim3(Hn/128, Fn/32, 1), 256>>>(w2, w216, Fn, Hn, (long)Fn*Hn, (long)Fn*Hn);
    embed_bias<<<MR + (Ln*QKVN + 255)/256, 256>>>(tok, emb, pos, x, xf, bq, bk, bv, bqkv);

    // ---- layers 1..5 weight conversion on side stream ----
    cudaEventRecord(ev1, 0);
    cudaStreamWaitEvent(s2, ev1, 0);
    wconv4<<<dim3(Hn/128, Hn/32, 4*(Ln-1)), 256, 0, s2>>>(wq, wk, wv, wo, wqkv16, wo16, 4);
    wconv<<<dim3(Fn/128, Hn/32, Ln-1), 256, 0, s2>>>(
        w1 + (size_t)Hn*Fn, w116 + (size_t)Hn*Fn, Hn, Fn, (long)Hn*Fn, (long)Hn*Fn);
    wconv<<<dim3(Hn/128, Fn/32, Ln-1), 256, 0, s2>>>(
        w2 + (size_t)Fn*Hn, w216 + (size_t)Fn*Hn, Fn, Hn, (long)Fn*Hn, (long)Fn*Hn);
    cudaEventRecord(ev2, s2);

    for (int l = 0; l < Ln; l++) {
        if (l == 1) cudaStreamWaitEvent(0, ev2, 0);
        float* attnL = attn_out + (size_t)l * BH * Sn * Sn;
        bool last = (l == Ln - 1);
        float* lnout = last ? out : x;

        // fused QKV projection (fp16, f32 accum)
        gemm1<128,128,0,0><<<dim3(QKVN/128, MR/128), 512, SMEM_G1B>>>(
            xf, Hn, wqkv16 + (size_t)l * QKVN * Hn, Hn, nullptr, qkv16, QKVN,
            bqkv + (size_t)l * QKVN, Hn);

        // scores + softmax + P@V
        attn_fused<<<dim3(Sn/64, BH), 256, SMEM_ATT>>>(qkv16, tok, attnL, ct);

        // Wo split-K=2 -> fp32 partials
        gemm1<64,128,5,0><<<dim3(Hn/128, MR/64, 2), 512, SMEM_G1A>>>(
            ct, Hn, wo16 + (size_t)l * Hn * Hn, Hn, y, nullptr, Hn, nullptr, Hn);
        layernorm_sum<<<MR/8, 256>>>(y, y + (size_t)MR*Hn, bo + (size_t)l * Hn, x,
                                     g1 + (size_t)l * Hn, be1 + (size_t)l * Hn, x, xf);

        // FFN1 (relu) — fp16-accumulator experiment
        gemm1<128,128,4,1><<<dim3(Fn/128, MR/128), 512, SMEM_G1B>>>(
            xf, Hn, w116 + (size_t)l * Hn * Fn, Hn, nullptr, f16, Fn,
            b1 + (size_t)l * Fn, Hn);

        // FFN2 split-K=2 -> fp32 partials
        gemm1<64,128,5,0><<<dim3(Hn/128, MR/64, 2), 512, SMEM_G1A>>>(
            f16, Fn, w216 + (size_t)l * Fn * Hn, Fn, y, nullptr, Hn, nullptr, Fn);
        layernorm_sum<<<MR/8, 256>>>(y, y + (size_t)MR*Hn, b2 + (size_t)l * Hn, x,
                                     g2 + (size_t)l * Hn, be2 + (size_t)l * Hn, lnout, xf);
    }
}

// round 13
// speedup vs baseline: 1.0477x; 1.0477x over previous
#include <cuda_runtime.h>
#include <cuda_bf16.h>
#include <cuda_fp16.h>

typedef unsigned int u32;
typedef unsigned long long u64;

#define Bn 4
#define Sn 512
#define Hn 768
#define NHn 12
#define Fn 3072
#define Ln 6
#define MR (Bn*Sn)          // 2048
#define QKVN 2304
#define BH (Bn*NHn)         // 48

// ---------------- scratch (device globals) ----------------
__device__ __half g_wqkv16[(size_t)Ln*QKVN*Hn];
__device__ __half g_wo16[(size_t)Ln*Hn*Hn];
__device__ __half g_w116[(size_t)Ln*Hn*Fn];
__device__ __half g_w216[(size_t)Ln*Fn*Hn];
__device__ float g_x[MR*Hn];
__device__ float g_y[2*MR*Hn];                 // split-K partials (fp32)
__device__ float g_bqkv[Ln*QKVN];
__device__ __half g_xf[MR*Hn];
__device__ __half g_qkv16[(size_t)MR*QKVN];
__device__ __half g_ct16[MR*Hn];
__device__ __half g_f16[(size_t)MR*Fn];

// ---------------- helpers ----------------
__device__ __forceinline__ u32 s2u(const void* p) {
    u32 a;
    asm("{ .reg .u64 t; cvta.to.shared.u64 t, %1; cvt.u32.u64 %0, t; }" : "=r"(a) : "l"(p));
    return a;
}
__device__ __forceinline__ u32 swz(u32 o) { return o ^ ((o >> 3) & 0x70); }

__device__ __forceinline__ void cpasync16(u32 dst, const void* src) {
    asm volatile("cp.async.cg.shared.global [%0], [%1], 16;" :: "r"(dst), "l"(src) : "memory");
}
__device__ __forceinline__ void ldsm4(u32& r0, u32& r1, u32& r2, u32& r3, u32 a) {
    asm volatile("ldmatrix.sync.aligned.m8n8.x4.shared.b16 {%0,%1,%2,%3}, [%4];"
                 : "=r"(r0), "=r"(r1), "=r"(r2), "=r"(r3) : "r"(a));
}
__device__ __forceinline__ void ldsm4t(u32& r0, u32& r1, u32& r2, u32& r3, u32 a) {
    asm volatile("ldmatrix.sync.aligned.m8n8.x4.trans.shared.b16 {%0,%1,%2,%3}, [%4];"
                 : "=r"(r0), "=r"(r1), "=r"(r2), "=r"(r3) : "r"(a));
}
__device__ __forceinline__ void mma16816h(float* c, const u32* a, const u32* b) {
    asm volatile("mma.sync.aligned.m16n8k16.row.col.f32.f16.f16.f32 "
                 "{%0,%1,%2,%3}, {%4,%5,%6,%7}, {%8,%9}, {%0,%1,%2,%3};"
                 : "+f"(c[0]), "+f"(c[1]), "+f"(c[2]), "+f"(c[3])
                 : "r"(a[0]), "r"(a[1]), "r"(a[2]), "r"(a[3]), "r"(b[0]), "r"(b[1]));
}
__device__ __forceinline__ u32 packh2(float v0, float v1) {
    __half2 h = __floats2half2_rn(v0, v1);
    return *reinterpret_cast<u32*>(&h);
}

// ==================================================================
// fp16 single-pass GEMM. MT x NT, BK=64, 512 threads (16 warps 4x4).
// EPI: 0=bias->fp16  4=bias+relu->fp16  5=split-K raw partial -> fp32
// ==================================================================
template<int MT, int NT, int EPI>
__global__ void __launch_bounds__(512)
gemm1(const __half* __restrict__ A, int lda, const __half* __restrict__ B, int ldb,
      float* __restrict__ Cf, __half* __restrict__ Ch, int ldc,
      const float* __restrict__ bias, int K)
{
    constexpr int WM = MT / 4, WN = NT / 4;
    constexpr int MI = WM / 16, NI = WN / 8;
    constexpr u32 ASZ = (u32)MT * 128u, BSZ = (u32)NT * 128u;
    constexpr u32 STG = ASZ + BSZ;

    if (EPI == 5) {
        A += (size_t)blockIdx.z * (u32)(K >> 1);
        B += (size_t)blockIdx.z * (u32)(K >> 1);
        K >>= 1;
    }

    extern __shared__ char smem[];
    const u32 sb = s2u(smem);
    const int tid = threadIdx.x, wid = tid >> 5, lane = tid & 31;
    const int warp_m = wid >> 2, warp_n = wid & 3;
    const int m0 = blockIdx.y * MT, n0 = blockIdx.x * NT;
    const int nsl = K >> 6;

    float acc[MI][NI][4];
#pragma unroll
    for (int mi = 0; mi < MI; mi++)
#pragma unroll
        for (int ni = 0; ni < NI; ni++)
#pragma unroll
            for (int q = 0; q < 4; q++) acc[mi][ni][q] = 0.f;

    auto prefetch = [&](int sl) {
        const u32 base = sb + (u32)(sl % 3) * STG;
#pragma unroll
        for (int i = 0; i < MT * 8 / 512; i++) {
            int u = tid + i * 512;
            int r = u >> 3, c = u & 7;
            cpasync16(base + swz((u32)(r * 128 + c * 16)),
                      A + (size_t)(m0 + r) * lda + sl * 64 + c * 8);
        }
#pragma unroll
        for (int i = 0; i < NT * 8 / 512; i++) {
            int u = tid + i * 512;
            int r = u >> 3, c = u & 7;
            cpasync16(base + ASZ + swz((u32)(r * 128 + c * 16)),
                      B + (size_t)(n0 + r) * ldb + sl * 64 + c * 8);
        }
        asm volatile("cp.async.commit_group;" ::: "memory");
    };

    prefetch(0); prefetch(1);

    for (int it = 0; it < nsl; it++) {
        if (it < nsl - 1) asm volatile("cp.async.wait_group 1;" ::: "memory");
        else              asm volatile("cp.async.wait_group 0;" ::: "memory");
        __syncthreads();
        if (it + 2 < nsl) prefetch(it + 2);

        const u32 ab = sb + (u32)(it % 3) * STG;
        const u32 bb = ab + ASZ;

#pragma unroll
        for (int ks = 0; ks < 4; ks++) {
            u32 ar[MI][4];
#pragma unroll
            for (int mi = 0; mi < MI; mi++) {
                int row = warp_m * WM + mi * 16 + (lane & 15);
                u32 off = swz((u32)(row * 128 + (ks * 16 + (lane >> 4) * 8) * 2));
                ldsm4(ar[mi][0], ar[mi][1], ar[mi][2], ar[mi][3], ab + off);
            }
            u32 br[NI][2];
#pragma unroll
            for (int nj = 0; nj < NI / 2; nj++) {
                int nrow = warp_n * WN + nj * 16 + (lane & 7) + ((lane >> 4) << 3);
                u32 off = swz((u32)(nrow * 128 + (ks * 16 + ((lane >> 3) & 1) * 8) * 2));
                u32 r0, r1, r2, r3;
                ldsm4(r0, r1, r2, r3, bb + off);
                br[2 * nj][0] = r0; br[2 * nj][1] = r1;
                br[2 * nj + 1][0] = r2; br[2 * nj + 1][1] = r3;
            }
#pragma unroll
            for (int mi = 0; mi < MI; mi++)
#pragma unroll
                for (int ni = 0; ni < NI; ni++)
                    mma16816h(acc[mi][ni], ar[mi], br[ni]);
        }
    }

    const int tg = lane & 3, g = lane >> 2;
    const size_t zoff = (EPI == 5) ? (size_t)blockIdx.z * MR * ldc : 0;
#pragma unroll
    for (int mi = 0; mi < MI; mi++)
#pragma unroll
        for (int half = 0; half < 2; half++) {
            const int mrow = m0 + warp_m * WM + mi * 16 + half * 8 + g;
#pragma unroll
            for (int ni = 0; ni < NI; ni++) {
                const int col = n0 + warp_n * WN + ni * 8 + tg * 2;
                float v0 = acc[mi][ni][half * 2];
                float v1 = acc[mi][ni][half * 2 + 1];
                size_t off = (size_t)mrow * ldc + col;
                if (EPI == 5) {
                    *(float2*)(Cf + zoff + off) = make_float2(v0, v1);
                } else {
                    v0 += bias[col]; v1 += bias[col + 1];
                    if (EPI == 4) { v0 = fmaxf(v0, 0.f); v1 = fmaxf(v1, 0.f); }
                    *(u32*)(Ch + off) = packh2(v0, v1);
                }
            }
        }
}

// ==================================================================
// Fused attention (all fp16): scores + softmax + P@V. 64 q-rows/(b,h).
// smem: Q[0,8K)  K[8K,72K)->P  V[72K,136K)  red[136K..]
// ==================================================================
#define ATT_KP   8192u
#define ATT_V    73728u
#define ATT_RED  139264
#define SMEM_ATT (ATT_RED + 2048)

__global__ void __launch_bounds__(256)
attn_fused(const __half* __restrict__ qkv, const int* __restrict__ tok,
           float* __restrict__ attn, __half* __restrict__ ct)
{
    extern __shared__ char smem[];
    const u32 sb = s2u(smem);
    const int tid = threadIdx.x, wid = tid >> 5, lane = tid & 31;
    const int g = lane >> 2, tg = lane & 3;
    const int m0 = blockIdx.x * 64;
    const int zbh = blockIdx.y;
    const int b = zbh / NHn, h = zbh - b * NHn;

    const __half* Q_src = qkv + (size_t)(b * Sn + m0) * QKVN + h * 64;
    const __half* K_src = qkv + (size_t)(b * Sn) * QKVN + 768 + h * 64;
    const __half* V_src = qkv + (size_t)(b * Sn) * QKVN + 1536 + h * 64;

    for (int u = tid; u < 512; u += 256) {
        int r = u >> 3, c = u & 7;
        cpasync16(sb + swz((u32)(r * 128 + c * 16)), Q_src + (size_t)r * QKVN + c * 8);
    }
    for (int u = tid; u < 4096; u += 256) {
        int r = u >> 3, c = u & 7;
        cpasync16(sb + ATT_KP + swz((u32)(r * 128 + c * 16)), K_src + (size_t)r * QKVN + c * 8);
    }
    asm volatile("cp.async.commit_group;" ::: "memory");
    for (int u = tid; u < 4096; u += 256) {
        int r = u >> 3, c = u & 7;
        cpasync16(sb + ATT_V + swz((u32)(r * 128 + c * 16)), V_src + (size_t)r * QKVN + c * 8);
    }
    asm volatile("cp.async.commit_group;" ::: "memory");

    asm volatile("cp.async.wait_group 1;" ::: "memory");
    __syncthreads();

    // ---- scores = Q K^T ----
    float acc[4][8][4];
#pragma unroll
    for (int mi = 0; mi < 4; mi++)
#pragma unroll
        for (int ni = 0; ni < 8; ni++)
#pragma unroll
            for (int q = 0; q < 4; q++) acc[mi][ni][q] = 0.f;

#pragma unroll
    for (int ks = 0; ks < 4; ks++) {
        u32 arg[4][4];
#pragma unroll
        for (int mi = 0; mi < 4; mi++) {
            int row = mi * 16 + (lane & 15);
            u32 off = swz((u32)(row * 128 + (ks * 16 + (lane >> 4) * 8) * 2));
            ldsm4(arg[mi][0], arg[mi][1], arg[mi][2], arg[mi][3], sb + off);
        }
        u32 brg[8][2];
#pragma unroll
        for (int nj = 0; nj < 4; nj++) {
            int nrow = wid * 64 + nj * 16 + (lane & 7) + ((lane >> 4) << 3);
            u32 off = swz((u32)(nrow * 128 + (ks * 16 + ((lane >> 3) & 1) * 8) * 2));
            u32 r0, r1, r2, r3;
            ldsm4(r0, r1, r2, r3, sb + ATT_KP + off);
            brg[2 * nj][0] = r0; brg[2 * nj][1] = r1;
            brg[2 * nj + 1][0] = r2; brg[2 * nj + 1][1] = r3;
        }
#pragma unroll
        for (int mi = 0; mi < 4; mi++)
#pragma unroll
            for (int ni = 0; ni < 8; ni++)
                mma16816h(acc[mi][ni], arg[mi], brg[ni]);
    }
    __syncthreads();

    // ---- scale + mask + exp (no max-sub; logits small, mask underflows) ----
    float mk[8][2];
#pragma unroll
    for (int ni = 0; ni < 8; ni++) {
        int c = wid * 64 + ni * 8 + tg * 2;
        mk[ni][0] = (tok[b * Sn + c]     == 0) ? -10000.f : 0.f;
        mk[ni][1] = (tok[b * Sn + c + 1] == 0) ? -10000.f : 0.f;
    }

    float* red = (float*)(smem + ATT_RED);
    float rsum[8];

#pragma unroll
    for (int mi = 0; mi < 4; mi++)
#pragma unroll
        for (int half = 0; half < 2; half++) {
            float s = 0.f;
#pragma unroll
            for (int ni = 0; ni < 8; ni++) {
                float e0 = __expf(acc[mi][ni][half * 2]     * 0.125f + mk[ni][0]);
                float e1 = __expf(acc[mi][ni][half * 2 + 1] * 0.125f + mk[ni][1]);
                acc[mi][ni][half * 2] = e0; acc[mi][ni][half * 2 + 1] = e1;
                s += e0 + e1;
            }
            s += __shfl_xor_sync(0xffffffffu, s, 1);
            s += __shfl_xor_sync(0xffffffffu, s, 2);
            int row = mi * 16 + half * 8 + g;
            if (tg == 0) red[row * 8 + wid] = s;
        }
    __syncthreads();
#pragma unroll
    for (int mi = 0; mi < 4; mi++)
#pragma unroll
        for (int half = 0; half < 2; half++) {
            int row = mi * 16 + half * 8 + g;
            float s = 0.f;
#pragma unroll
            for (int w = 0; w < 8; w++) s += red[row * 8 + w];
            rsum[mi * 2 + half] = 1.f / s;
        }

    // ---- write attn fp32 + P fp16 into smem (8 slabs 64x64 over K) ----
#pragma unroll
    for (int mi = 0; mi < 4; mi++)
#pragma unroll
        for (int half = 0; half < 2; half++) {
            int row = mi * 16 + half * 8 + g;
            size_t rbase = (size_t)zbh * Sn * Sn + (size_t)(m0 + row) * Sn;
            float inv = rsum[mi * 2 + half];
#pragma unroll
            for (int ni = 0; ni < 8; ni++) {
                int col = ni * 8 + tg * 2;
                float p0 = acc[mi][ni][half * 2]     * inv;
                float p1 = acc[mi][ni][half * 2 + 1] * inv;
                *(float2*)(attn + rbase + wid * 64 + col) = make_float2(p0, p1);
                u32 off = (u32)(wid * 8192) + swz((u32)(row * 128 + col * 2));
                *(u32*)(smem + ATT_KP + off) = packh2(p0, p1);
            }
        }

    asm volatile("cp.async.wait_group 0;" ::: "memory");
    __syncthreads();

    // ---- ctx = P @ V (V via trans-ldmatrix) ----
    const int wm = wid >> 2, wn = wid & 3;
    float acc2[2][2][4];
#pragma unroll
    for (int mi = 0; mi < 2; mi++)
#pragma unroll
        for (int ni = 0; ni < 2; ni++)
#pragma unroll
            for (int q = 0; q < 4; q++) acc2[mi][ni][q] = 0.f;

#pragma unroll 2
    for (int sl = 0; sl < 8; sl++) {
#pragma unroll
        for (int ks = 0; ks < 4; ks++) {
            u32 ar[2][4];
#pragma unroll
            for (int mi = 0; mi < 2; mi++) {
                int row = wm * 32 + mi * 16 + (lane & 15);
                u32 aoff = (u32)(sl * 8192) + swz((u32)(row * 128 + (ks * 16 + (lane >> 4) * 8) * 2));
                ldsm4(ar[mi][0], ar[mi][1], ar[mi][2], ar[mi][3], sb + ATT_KP + aoff);
            }
            int srow = sl * 64 + ks * 16 + (lane & 7) + ((lane >> 3) & 1) * 8;
            int dcol = wn * 16 + ((lane >> 4) << 3);
            u32 boff = swz((u32)(srow * 128 + dcol * 2));
            u32 br[2][2], r0, r1, r2, r3;
            ldsm4t(r0, r1, r2, r3, sb + ATT_V + boff);
            br[0][0] = r0; br[0][1] = r1; br[1][0] = r2; br[1][1] = r3;
#pragma unroll
            for (int mi = 0; mi < 2; mi++)
#pragma unroll
                for (int ni = 0; ni < 2; ni++)
                    mma16816h(acc2[mi][ni], ar[mi], br[ni]);
        }
    }

#pragma unroll
    for (int mi = 0; mi < 2; mi++)
#pragma unroll
        for (int half = 0; half < 2; half++) {
            int row = m0 + wm * 32 + mi * 16 + half * 8 + g;
#pragma unroll
            for (int ni = 0; ni < 2; ni++) {
                int col = wn * 16 + ni * 8 + tg * 2;
                size_t off = (size_t)(b * Sn + row) * Hn + h * 64 + col;
                *(u32*)(ct + off) = packh2(acc2[mi][ni][half * 2], acc2[mi][ni][half * 2 + 1]);
            }
        }
}

// ==================================================================
// weight convert+transpose: fp32 [K,N] -> fp16 [N,K]
// ==================================================================
__global__ void __launch_bounds__(256)
wconv(const float* __restrict__ src0, __half* __restrict__ dst0,
      int K, int N, long in_l, long out_l)
{
    __shared__ float t[32][132];
    const float* src = src0 + (size_t)blockIdx.z * in_l;
    __half* dst = dst0 + (size_t)blockIdx.z * out_l;
    const int n0 = blockIdx.x * 128, k0 = blockIdx.y * 32;
    const int tid = threadIdx.x;

#pragma unroll
    for (int i = 0; i < 4; i++) {
        int idx = tid + i * 256;
        int r = idx >> 5, c = (idx & 31) << 2;
        float4 v = *(const float4*)(src + (size_t)(k0 + r) * N + n0 + c);
        t[r][c] = v.x; t[r][c + 1] = v.y; t[r][c + 2] = v.z; t[r][c + 3] = v.w;
    }
    __syncthreads();
#pragma unroll
    for (int i = 0; i < 4; i++) {
        int idx = tid + i * 256;
        int n = idx >> 3, ks = (idx & 7) << 2;
        u32 p0 = packh2(t[ks][n],     t[ks + 1][n]);
        u32 p1 = packh2(t[ks + 2][n], t[ks + 3][n]);
        size_t off = (size_t)(n0 + n) * K + k0 + ks;
        *(u32*)(dst + off)     = p0;
        *(u32*)(dst + off + 2) = p1;
    }
}

// merged variant for the 4 HxH weights; zoff selects entry range
__global__ void __launch_bounds__(256)
wconv4(const float* __restrict__ wq, const float* __restrict__ wk,
       const float* __restrict__ wv, const float* __restrict__ wo,
       __half* __restrict__ oqkv, __half* __restrict__ owo, int zoff)
{
    __shared__ float t[32][132];
    int z = blockIdx.z + zoff, l = z >> 2, which = z & 3;
    const float* src = (which == 0 ? wq : which == 1 ? wk : which == 2 ? wv : wo)
                       + (size_t)l * Hn * Hn;
    __half* dst;
    size_t obase;
    if (which < 3) { dst = oqkv; obase = (size_t)l * QKVN * Hn + (size_t)which * 768 * Hn; }
    else           { dst = owo;  obase = (size_t)l * Hn * Hn; }
    const int n0 = blockIdx.x * 128, k0 = blockIdx.y * 32;
    const int tid = threadIdx.x;

#pragma unroll
    for (int i = 0; i < 4; i++) {
        int idx = tid + i * 256;
        int r = idx >> 5, c = (idx & 31) << 2;
        float4 v = *(const float4*)(src + (size_t)(k0 + r) * Hn + n0 + c);
        t[r][c] = v.x; t[r][c + 1] = v.y; t[r][c + 2] = v.z; t[r][c + 3] = v.w;
    }
    __syncthreads();
#pragma unroll
    for (int i = 0; i < 4; i++) {
        int idx = tid + i * 256;
        int n = idx >> 3, ks = (idx & 7) << 2;
        u32 p0 = packh2(t[ks][n],     t[ks + 1][n]);
        u32 p1 = packh2(t[ks + 2][n], t[ks + 3][n]);
        size_t off = obase + (size_t)(n0 + n) * Hn + k0 + ks;
        *(u32*)(dst + off)     = p0;
        *(u32*)(dst + off + 2) = p1;
    }
}

// embed + biaspack merged
__global__ void embed_bias(const int* __restrict__ tok, const float* __restrict__ emb,
                           const float* __restrict__ pos, float* __restrict__ x,
                           __half* __restrict__ xf,
                           const float* __restrict__ bq, const float* __restrict__ bk,
                           const float* __restrict__ bv, float* __restrict__ obias) {
    if (blockIdx.x < MR) {
        int row = blockIdx.x;
        int t = tok[row];
        const float* e = emb + (size_t)t * Hn;
        const float* p = pos + (size_t)(row % Sn) * Hn;
        size_t base = (size_t)row * Hn;
        for (int c = threadIdx.x; c < Hn; c += blockDim.x) {
            float v = e[c] + p[c];
            x[base + c] = v;
            xf[base + c] = __float2half(v);
        }
    } else {
        int i = (blockIdx.x - MR) * 256 + threadIdx.x;
        if (i < Ln * QKVN) {
            int l = i / QKVN, n = i - l * QKVN;
            float v = (n < 768) ? bq[l * Hn + n]
                    : (n < 1536) ? bk[l * Hn + n - 768] : bv[l * Hn + n - 1536];
            obias[i] = v;
        }
    }
}

// ==================================================================
// warp-per-row layernorm over (y0 + y1 + bias + resid), fp32 partials
// ==================================================================
__global__ void __launch_bounds__(256)
layernorm_sum(const float* __restrict__ y0, const float* __restrict__ y1,
              const float* __restrict__ bias, const float* __restrict__ resid,
              const float* __restrict__ g, const float* __restrict__ be,
              float* __restrict__ out, __half* __restrict__ of) {
    const int row = blockIdx.x * 8 + (threadIdx.x >> 5);
    const int lane = threadIdx.x & 31;
    const size_t rb = (size_t)row * Hn;

    float4 v[6];
    float s = 0.f, sq = 0.f;
#pragma unroll
    for (int i = 0; i < 6; i++) {
        int idx = i * 128 + lane * 4;
        float4 a0 = *(const float4*)(y0 + rb + idx);
        float4 a1 = *(const float4*)(y1 + rb + idx);
        float4 bv = *(const float4*)(bias + idx);
        float4 rv = *(const float4*)(resid + rb + idx);
        v[i].x = a0.x + a1.x + bv.x + rv.x;
        v[i].y = a0.y + a1.y + bv.y + rv.y;
        v[i].z = a0.z + a1.z + bv.z + rv.z;
        v[i].w = a0.w + a1.w + bv.w + rv.w;
        s  += v[i].x + v[i].y + v[i].z + v[i].w;
        sq += v[i].x * v[i].x + v[i].y * v[i].y + v[i].z * v[i].z + v[i].w * v[i].w;
    }
#pragma unroll
    for (int o = 16; o; o >>= 1) {
        s  += __shfl_xor_sync(0xffffffffu, s, o);
        sq += __shfl_xor_sync(0xffffffffu, sq, o);
    }
    float m = s * (1.0f / Hn);
    float var = sq * (1.0f / Hn) - m * m;
    float inv = rsqrtf(var + 1e-12f);

#pragma unroll
    for (int i = 0; i < 6; i++) {
        int idx = i * 128 + lane * 4;
        float4 gg = *(const float4*)(g + idx);
        float4 bb = *(const float4*)(be + idx);
        float4 r;
        r.x = (v[i].x - m) * inv * gg.x + bb.x;
        r.y = (v[i].y - m) * inv * gg.y + bb.y;
        r.z = (v[i].z - m) * inv * gg.z + bb.z;
        r.w = (v[i].w - m) * inv * gg.w + bb.w;
        *(float4*)(out + rb + idx) = r;
        u32 h0 = packh2(r.x, r.y), h1 = packh2(r.z, r.w);
        *(u32*)(of + rb + idx)     = h0;
        *(u32*)(of + rb + idx + 2) = h1;
    }
}

// ==================================================================
#define SMEM_G1B (3 * (128*128 + 128*128))       // 98304 (128x128)
#define SMEM_G1A (3 * (64*128  + 128*128))       // 73728 (64x128)

extern "C" void kernel_launch(void* const* d_in, const int* in_sizes, int n_in,
                              void* d_out, int out_size) {
    const int*   tok = (const int*)d_in[0];
    const float* emb = (const float*)d_in[1];
    const float* pos = (const float*)d_in[2];
    const float* wq  = (const float*)d_in[3];
    const float* bq  = (const float*)d_in[4];
    const float* wk  = (const float*)d_in[5];
    const float* bk  = (const float*)d_in[6];
    const float* wv  = (const float*)d_in[7];
    const float* bv  = (const float*)d_in[8];
    const float* wo  = (const float*)d_in[9];
    const float* bo  = (const float*)d_in[10];
    const float* g1  = (const float*)d_in[11];
    const float* be1 = (const float*)d_in[12];
    const float* w1  = (const float*)d_in[13];
    const float* b1  = (const float*)d_in[14];
    const float* w2  = (const float*)d_in[15];
    const float* b2  = (const float*)d_in[16];
    const float* g2  = (const float*)d_in[17];
    const float* be2 = (const float*)d_in[18];

    float* out      = (float*)d_out;
    float* attn_out = out + (size_t)MR * Hn;

    float *x, *y, *bqkv;
    __half *wqkv16, *wo16, *w116, *w216, *xf, *qkv16, *ct, *f16;
    cudaGetSymbolAddress((void**)&x, g_x);
    cudaGetSymbolAddress((void**)&y, g_y);
    cudaGetSymbolAddress((void**)&bqkv, g_bqkv);
    cudaGetSymbolAddress((void**)&wqkv16, g_wqkv16);
    cudaGetSymbolAddress((void**)&wo16, g_wo16);
    cudaGetSymbolAddress((void**)&w116, g_w116);
    cudaGetSymbolAddress((void**)&w216, g_w216);
    cudaGetSymbolAddress((void**)&xf, g_xf);
    cudaGetSymbolAddress((void**)&qkv16, g_qkv16);
    cudaGetSymbolAddress((void**)&ct, g_ct16);
    cudaGetSymbolAddress((void**)&f16, g_f16);

    cudaFuncSetAttribute(gemm1<128,128,0>, cudaFuncAttributeMaxDynamicSharedMemorySize, SMEM_G1B);
    cudaFuncSetAttribute(gemm1<64,128,5>,  cudaFuncAttributeMaxDynamicSharedMemorySize, SMEM_G1A);
    cudaFuncSetAttribute(gemm1<128,128,4>, cudaFuncAttributeMaxDynamicSharedMemorySize, SMEM_G1B);
    cudaFuncSetAttribute(attn_fused, cudaFuncAttributeMaxDynamicSharedMemorySize, SMEM_ATT);

    static cudaStream_t s2 = nullptr;
    static cudaEvent_t ev1 = nullptr, ev2 = nullptr;
    if (!s2) {
        cudaStreamCreateWithFlags(&s2, cudaStreamNonBlocking);
        cudaEventCreateWithFlags(&ev1, cudaEventDisableTiming);
        cudaEventCreateWithFlags(&ev2, cudaEventDisableTiming);
    }

    // ---- critical-path prologue: ONLY wq/wk/wv of layer 0 + embed ----
    wconv4<<<dim3(Hn/128, Hn/32, 3), 256>>>(wq, wk, wv, wo, wqkv16, wo16, 0);
    embed_bias<<<MR + (Ln*QKVN + 255)/256, 256>>>(tok, emb, pos, x, xf, bq, bk, bv, bqkv);

    // ---- side stream: everything else (wo l0 + layers 1..5 QKV/wo, all w1/w2) ----
    cudaEventRecord(ev1, 0);
    cudaStreamWaitEvent(s2, ev1, 0);
    wconv4<<<dim3(Hn/128, Hn/32, 4*Ln - 3), 256, 0, s2>>>(wq, wk, wv, wo, wqkv16, wo16, 3);
    wconv<<<dim3(Fn/128, Hn/32, Ln), 256, 0, s2>>>(w1, w116, Hn, Fn, (long)Hn*Fn, (long)Hn*Fn);
    wconv<<<dim3(Hn/128, Fn/32, Ln), 256, 0, s2>>>(w2, w216, Fn, Hn, (long)Fn*Hn, (long)Fn*Hn);
    cudaEventRecord(ev2, s2);

    for (int l = 0; l < Ln; l++) {
        float* attnL = attn_out + (size_t)l * BH * Sn * Sn;
        bool last = (l == Ln - 1);
        float* lnout = last ? out : x;

        // fused QKV projection (fp16)
        gemm1<128,128,0><<<dim3(QKVN/128, MR/128), 512, SMEM_G1B>>>(
            xf, Hn, wqkv16 + (size_t)l * QKVN * Hn, Hn, nullptr, qkv16, QKVN,
            bqkv + (size_t)l * QKVN, Hn);

        // scores + softmax + P@V
        attn_fused<<<dim3(Sn/64, BH), 256, SMEM_ATT>>>(qkv16, tok, attnL, ct);

        if (l == 0) cudaStreamWaitEvent(0, ev2, 0);   // remaining weights ready

        // Wo split-K=2 -> fp32 partials
        gemm1<64,128,5><<<dim3(Hn/128, MR/64, 2), 512, SMEM_G1A>>>(
            ct, Hn, wo16 + (size_t)l * Hn * Hn, Hn, y, nullptr, Hn, nullptr, Hn);
        layernorm_sum<<<MR/8, 256>>>(y, y + (size_t)MR*Hn, bo + (size_t)l * Hn, x,
                                     g1 + (size_t)l * Hn, be1 + (size_t)l * Hn, x, xf);

        // FFN1 (relu)
        gemm1<128,128,4><<<dim3(Fn/128, MR/128), 512, SMEM_G1B>>>(
            xf, Hn, w116 + (size_t)l * Hn * Fn, Hn, nullptr, f16, Fn,
            b1 + (size_t)l * Fn, Hn);

        // FFN2 split-K=2 -> fp32 partials
        gemm1<64,128,5><<<dim3(Hn/128, MR/64, 2), 512, SMEM_G1A>>>(
            f16, Fn, w216 + (size_t)l * Fn * Hn, Fn, y, nullptr, Hn, nullptr, Fn);
        layernorm_sum<<<MR/8, 256>>>(y, y + (size_t)MR*Hn, b2 + (size_t)l * Hn, x,
                                     g2 + (size_t)l * Hn, be2 + (size_t)l * Hn, lnout, xf);
    }
}

// round 14
// speedup vs baseline: 1.0715x; 1.0226x over previous
#include <cuda_runtime.h>
#include <cuda_bf16.h>
#include <cuda_fp16.h>

typedef unsigned int u32;
typedef unsigned long long u64;

#define Bn 4
#define Sn 512
#define Hn 768
#define NHn 12
#define Fn 3072
#define Ln 6
#define MR (Bn*Sn)          // 2048
#define QKVN 2304
#define BH (Bn*NHn)         // 48

// ---------------- scratch (device globals) ----------------
__device__ __half g_wqkv16[(size_t)Ln*QKVN*Hn];
__device__ __half g_wo16[(size_t)Ln*Hn*Hn];
__device__ __half g_w116[(size_t)Ln*Hn*Fn];
__device__ __half g_w216[(size_t)Ln*Fn*Hn];
__device__ float g_x[MR*Hn];
__device__ float g_y[3*MR*Hn];                 // split-K partials (fp32, 3-way)
__device__ float g_bqkv[Ln*QKVN];
__device__ __half g_xf[MR*Hn];
__device__ __half g_qkv16[(size_t)MR*QKVN];
__device__ __half g_ct16[MR*Hn];
__device__ __half g_f16[(size_t)MR*Fn];

// ---------------- helpers ----------------
__device__ __forceinline__ u32 s2u(const void* p) {
    u32 a;
    asm("{ .reg .u64 t; cvta.to.shared.u64 t, %1; cvt.u32.u64 %0, t; }" : "=r"(a) : "l"(p));
    return a;
}
__device__ __forceinline__ u32 swz(u32 o) { return o ^ ((o >> 3) & 0x70); }

__device__ __forceinline__ void cpasync16(u32 dst, const void* src) {
    asm volatile("cp.async.cg.shared.global [%0], [%1], 16;" :: "r"(dst), "l"(src) : "memory");
}
__device__ __forceinline__ void ldsm4(u32& r0, u32& r1, u32& r2, u32& r3, u32 a) {
    asm volatile("ldmatrix.sync.aligned.m8n8.x4.shared.b16 {%0,%1,%2,%3}, [%4];"
                 : "=r"(r0), "=r"(r1), "=r"(r2), "=r"(r3) : "r"(a));
}
__device__ __forceinline__ void ldsm4t(u32& r0, u32& r1, u32& r2, u32& r3, u32 a) {
    asm volatile("ldmatrix.sync.aligned.m8n8.x4.trans.shared.b16 {%0,%1,%2,%3}, [%4];"
                 : "=r"(r0), "=r"(r1), "=r"(r2), "=r"(r3) : "r"(a));
}
__device__ __forceinline__ void mma16816h(float* c, const u32* a, const u32* b) {
    asm volatile("mma.sync.aligned.m16n8k16.row.col.f32.f16.f16.f32 "
                 "{%0,%1,%2,%3}, {%4,%5,%6,%7}, {%8,%9}, {%0,%1,%2,%3};"
                 : "+f"(c[0]), "+f"(c[1]), "+f"(c[2]), "+f"(c[3])
                 : "r"(a[0]), "r"(a[1]), "r"(a[2]), "r"(a[3]), "r"(b[0]), "r"(b[1]));
}
__device__ __forceinline__ u32 packh2(float v0, float v1) {
    __half2 h = __floats2half2_rn(v0, v1);
    return *reinterpret_cast<u32*>(&h);
}

// ==================================================================
// fp16 single-pass GEMM. MT x NT, BK=64, 512 threads (16 warps 4x4).
// EPI: 0=bias->fp16  4=bias+relu->fp16  5=split-K/3 raw partial -> fp32
// ==================================================================
template<int MT, int NT, int EPI>
__global__ void __launch_bounds__(512)
gemm1(const __half* __restrict__ A, int lda, const __half* __restrict__ B, int ldb,
      float* __restrict__ Cf, __half* __restrict__ Ch, int ldc,
      const float* __restrict__ bias, int K)
{
    constexpr int WM = MT / 4, WN = NT / 4;
    constexpr int MI = WM / 16, NI = WN / 8;
    constexpr u32 ASZ = (u32)MT * 128u, BSZ = (u32)NT * 128u;
    constexpr u32 STG = ASZ + BSZ;

    if (EPI == 5) {            // split-K=3: this CTA handles a third of K
        int ks = K / 3;
        A += (size_t)blockIdx.z * (u32)ks;
        B += (size_t)blockIdx.z * (u32)ks;
        K = ks;
    }

    extern __shared__ char smem[];
    const u32 sb = s2u(smem);
    const int tid = threadIdx.x, wid = tid >> 5, lane = tid & 31;
    const int warp_m = wid >> 2, warp_n = wid & 3;
    const int m0 = blockIdx.y * MT, n0 = blockIdx.x * NT;
    const int nsl = K >> 6;

    float acc[MI][NI][4];
#pragma unroll
    for (int mi = 0; mi < MI; mi++)
#pragma unroll
        for (int ni = 0; ni < NI; ni++)
#pragma unroll
            for (int q = 0; q < 4; q++) acc[mi][ni][q] = 0.f;

    auto prefetch = [&](int sl) {
        const u32 base = sb + (u32)(sl % 3) * STG;
#pragma unroll
        for (int i = 0; i < MT * 8 / 512; i++) {
            int u = tid + i * 512;
            int r = u >> 3, c = u & 7;
            cpasync16(base + swz((u32)(r * 128 + c * 16)),
                      A + (size_t)(m0 + r) * lda + sl * 64 + c * 8);
        }
#pragma unroll
        for (int i = 0; i < NT * 8 / 512; i++) {
            int u = tid + i * 512;
            int r = u >> 3, c = u & 7;
            cpasync16(base + ASZ + swz((u32)(r * 128 + c * 16)),
                      B + (size_t)(n0 + r) * ldb + sl * 64 + c * 8);
        }
        asm volatile("cp.async.commit_group;" ::: "memory");
    };

    prefetch(0); prefetch(1);

    for (int it = 0; it < nsl; it++) {
        if (it < nsl - 1) asm volatile("cp.async.wait_group 1;" ::: "memory");
        else              asm volatile("cp.async.wait_group 0;" ::: "memory");
        __syncthreads();
        if (it + 2 < nsl) prefetch(it + 2);

        const u32 ab = sb + (u32)(it % 3) * STG;
        const u32 bb = ab + ASZ;

#pragma unroll
        for (int ks = 0; ks < 4; ks++) {
            u32 ar[MI][4];
#pragma unroll
            for (int mi = 0; mi < MI; mi++) {
                int row = warp_m * WM + mi * 16 + (lane & 15);
                u32 off = swz((u32)(row * 128 + (ks * 16 + (lane >> 4) * 8) * 2));
                ldsm4(ar[mi][0], ar[mi][1], ar[mi][2], ar[mi][3], ab + off);
            }
            u32 br[NI][2];
#pragma unroll
            for (int nj = 0; nj < NI / 2; nj++) {
                int nrow = warp_n * WN + nj * 16 + (lane & 7) + ((lane >> 4) << 3);
                u32 off = swz((u32)(nrow * 128 + (ks * 16 + ((lane >> 3) & 1) * 8) * 2));
                u32 r0, r1, r2, r3;
                ldsm4(r0, r1, r2, r3, bb + off);
                br[2 * nj][0] = r0; br[2 * nj][1] = r1;
                br[2 * nj + 1][0] = r2; br[2 * nj + 1][1] = r3;
            }
#pragma unroll
            for (int mi = 0; mi < MI; mi++)
#pragma unroll
                for (int ni = 0; ni < NI; ni++)
                    mma16816h(acc[mi][ni], ar[mi], br[ni]);
        }
    }

    const int tg = lane & 3, g = lane >> 2;
    const size_t zoff = (EPI == 5) ? (size_t)blockIdx.z * MR * ldc : 0;
#pragma unroll
    for (int mi = 0; mi < MI; mi++)
#pragma unroll
        for (int half = 0; half < 2; half++) {
            const int mrow = m0 + warp_m * WM + mi * 16 + half * 8 + g;
#pragma unroll
            for (int ni = 0; ni < NI; ni++) {
                const int col = n0 + warp_n * WN + ni * 8 + tg * 2;
                float v0 = acc[mi][ni][half * 2];
                float v1 = acc[mi][ni][half * 2 + 1];
                size_t off = (size_t)mrow * ldc + col;
                if (EPI == 5) {
                    *(float2*)(Cf + zoff + off) = make_float2(v0, v1);
                } else {
                    v0 += bias[col]; v1 += bias[col + 1];
                    if (EPI == 4) { v0 = fmaxf(v0, 0.f); v1 = fmaxf(v1, 0.f); }
                    *(u32*)(Ch + off) = packh2(v0, v1);
                }
            }
        }
}

// ==================================================================
// Fused attention (all fp16): scores + softmax + P@V. 64 q-rows/(b,h).
// smem: Q[0,8K)  K[8K,72K)->P  V[72K,136K)  red[136K..]
// ==================================================================
#define ATT_KP   8192u
#define ATT_V    73728u
#define ATT_RED  139264
#define SMEM_ATT (ATT_RED + 2048)

__global__ void __launch_bounds__(256)
attn_fused(const __half* __restrict__ qkv, const int* __restrict__ tok,
           float* __restrict__ attn, __half* __restrict__ ct)
{
    extern __shared__ char smem[];
    const u32 sb = s2u(smem);
    const int tid = threadIdx.x, wid = tid >> 5, lane = tid & 31;
    const int g = lane >> 2, tg = lane & 3;
    const int m0 = blockIdx.x * 64;
    const int zbh = blockIdx.y;
    const int b = zbh / NHn, h = zbh - b * NHn;

    const __half* Q_src = qkv + (size_t)(b * Sn + m0) * QKVN + h * 64;
    const __half* K_src = qkv + (size_t)(b * Sn) * QKVN + 768 + h * 64;
    const __half* V_src = qkv + (size_t)(b * Sn) * QKVN + 1536 + h * 64;

    for (int u = tid; u < 512; u += 256) {
        int r = u >> 3, c = u & 7;
        cpasync16(sb + swz((u32)(r * 128 + c * 16)), Q_src + (size_t)r * QKVN + c * 8);
    }
    for (int u = tid; u < 4096; u += 256) {
        int r = u >> 3, c = u & 7;
        cpasync16(sb + ATT_KP + swz((u32)(r * 128 + c * 16)), K_src + (size_t)r * QKVN + c * 8);
    }
    asm volatile("cp.async.commit_group;" ::: "memory");
    for (int u = tid; u < 4096; u += 256) {
        int r = u >> 3, c = u & 7;
        cpasync16(sb + ATT_V + swz((u32)(r * 128 + c * 16)), V_src + (size_t)r * QKVN + c * 8);
    }
    asm volatile("cp.async.commit_group;" ::: "memory");

    asm volatile("cp.async.wait_group 1;" ::: "memory");
    __syncthreads();

    // ---- scores = Q K^T ----
    float acc[4][8][4];
#pragma unroll
    for (int mi = 0; mi < 4; mi++)
#pragma unroll
        for (int ni = 0; ni < 8; ni++)
#pragma unroll
            for (int q = 0; q < 4; q++) acc[mi][ni][q] = 0.f;

#pragma unroll
    for (int ks = 0; ks < 4; ks++) {
        u32 arg[4][4];
#pragma unroll
        for (int mi = 0; mi < 4; mi++) {
            int row = mi * 16 + (lane & 15);
            u32 off = swz((u32)(row * 128 + (ks * 16 + (lane >> 4) * 8) * 2));
            ldsm4(arg[mi][0], arg[mi][1], arg[mi][2], arg[mi][3], sb + off);
        }
        u32 brg[8][2];
#pragma unroll
        for (int nj = 0; nj < 4; nj++) {
            int nrow = wid * 64 + nj * 16 + (lane & 7) + ((lane >> 4) << 3);
            u32 off = swz((u32)(nrow * 128 + (ks * 16 + ((lane >> 3) & 1) * 8) * 2));
            u32 r0, r1, r2, r3;
            ldsm4(r0, r1, r2, r3, sb + ATT_KP + off);
            brg[2 * nj][0] = r0; brg[2 * nj][1] = r1;
            brg[2 * nj + 1][0] = r2; brg[2 * nj + 1][1] = r3;
        }
#pragma unroll
        for (int mi = 0; mi < 4; mi++)
#pragma unroll
            for (int ni = 0; ni < 8; ni++)
                mma16816h(acc[mi][ni], arg[mi], brg[ni]);
    }
    __syncthreads();

    // ---- scale + mask + exp (no max-sub; logits small, mask underflows) ----
    float mk[8][2];
#pragma unroll
    for (int ni = 0; ni < 8; ni++) {
        int c = wid * 64 + ni * 8 + tg * 2;
        mk[ni][0] = (tok[b * Sn + c]     == 0) ? -10000.f : 0.f;
        mk[ni][1] = (tok[b * Sn + c + 1] == 0) ? -10000.f : 0.f;
    }

    float* red = (float*)(smem + ATT_RED);
    float rsum[8];

#pragma unroll
    for (int mi = 0; mi < 4; mi++)
#pragma unroll
        for (int half = 0; half < 2; half++) {
            float s = 0.f;
#pragma unroll
            for (int ni = 0; ni < 8; ni++) {
                float e0 = __expf(acc[mi][ni][half * 2]     * 0.125f + mk[ni][0]);
                float e1 = __expf(acc[mi][ni][half * 2 + 1] * 0.125f + mk[ni][1]);
                acc[mi][ni][half * 2] = e0; acc[mi][ni][half * 2 + 1] = e1;
                s += e0 + e1;
            }
            s += __shfl_xor_sync(0xffffffffu, s, 1);
            s += __shfl_xor_sync(0xffffffffu, s, 2);
            int row = mi * 16 + half * 8 + g;
            if (tg == 0) red[row * 8 + wid] = s;
        }
    __syncthreads();
#pragma unroll
    for (int mi = 0; mi < 4; mi++)
#pragma unroll
        for (int half = 0; half < 2; half++) {
            int row = mi * 16 + half * 8 + g;
            float s = 0.f;
#pragma unroll
            for (int w = 0; w < 8; w++) s += red[row * 8 + w];
            rsum[mi * 2 + half] = 1.f / s;
        }

    // ---- write attn fp32 + P fp16 into smem (8 slabs 64x64 over K) ----
#pragma unroll
    for (int mi = 0; mi < 4; mi++)
#pragma unroll
        for (int half = 0; half < 2; half++) {
            int row = mi * 16 + half * 8 + g;
            size_t rbase = (size_t)zbh * Sn * Sn + (size_t)(m0 + row) * Sn;
            float inv = rsum[mi * 2 + half];
#pragma unroll
            for (int ni = 0; ni < 8; ni++) {
                int col = ni * 8 + tg * 2;
                float p0 = acc[mi][ni][half * 2]     * inv;
                float p1 = acc[mi][ni][half * 2 + 1] * inv;
                *(float2*)(attn + rbase + wid * 64 + col) = make_float2(p0, p1);
                u32 off = (u32)(wid * 8192) + swz((u32)(row * 128 + col * 2));
                *(u32*)(smem + ATT_KP + off) = packh2(p0, p1);
            }
        }

    asm volatile("cp.async.wait_group 0;" ::: "memory");
    __syncthreads();

    // ---- ctx = P @ V (V via trans-ldmatrix) ----
    const int wm = wid >> 2, wn = wid & 3;
    float acc2[2][2][4];
#pragma unroll
    for (int mi = 0; mi < 2; mi++)
#pragma unroll
        for (int ni = 0; ni < 2; ni++)
#pragma unroll
            for (int q = 0; q < 4; q++) acc2[mi][ni][q] = 0.f;

#pragma unroll 2
    for (int sl = 0; sl < 8; sl++) {
#pragma unroll
        for (int ks = 0; ks < 4; ks++) {
            u32 ar[2][4];
#pragma unroll
            for (int mi = 0; mi < 2; mi++) {
                int row = wm * 32 + mi * 16 + (lane & 15);
                u32 aoff = (u32)(sl * 8192) + swz((u32)(row * 128 + (ks * 16 + (lane >> 4) * 8) * 2));
                ldsm4(ar[mi][0], ar[mi][1], ar[mi][2], ar[mi][3], sb + ATT_KP + aoff);
            }
            int srow = sl * 64 + ks * 16 + (lane & 7) + ((lane >> 3) & 1) * 8;
            int dcol = wn * 16 + ((lane >> 4) << 3);
            u32 boff = swz((u32)(srow * 128 + dcol * 2));
            u32 br[2][2], r0, r1, r2, r3;
            ldsm4t(r0, r1, r2, r3, sb + ATT_V + boff);
            br[0][0] = r0; br[0][1] = r1; br[1][0] = r2; br[1][1] = r3;
#pragma unroll
            for (int mi = 0; mi < 2; mi++)
#pragma unroll
                for (int ni = 0; ni < 2; ni++)
                    mma16816h(acc2[mi][ni], ar[mi], br[ni]);
        }
    }

#pragma unroll
    for (int mi = 0; mi < 2; mi++)
#pragma unroll
        for (int half = 0; half < 2; half++) {
            int row = m0 + wm * 32 + mi * 16 + half * 8 + g;
#pragma unroll
            for (int ni = 0; ni < 2; ni++) {
                int col = wn * 16 + ni * 8 + tg * 2;
                size_t off = (size_t)(b * Sn + row) * Hn + h * 64 + col;
                *(u32*)(ct + off) = packh2(acc2[mi][ni][half * 2], acc2[mi][ni][half * 2 + 1]);
            }
        }
}

// ==================================================================
// weight convert+transpose: fp32 [K,N] -> fp16 [N,K]
// ==================================================================
__global__ void __launch_bounds__(256)
wconv(const float* __restrict__ src0, __half* __restrict__ dst0,
      int K, int N, long in_l, long out_l)
{
    __shared__ float t[32][132];
    const float* src = src0 + (size_t)blockIdx.z * in_l;
    __half* dst = dst0 + (size_t)blockIdx.z * out_l;
    const int n0 = blockIdx.x * 128, k0 = blockIdx.y * 32;
    const int tid = threadIdx.x;

#pragma unroll
    for (int i = 0; i < 4; i++) {
        int idx = tid + i * 256;
        int r = idx >> 5, c = (idx & 31) << 2;
        float4 v = *(const float4*)(src + (size_t)(k0 + r) * N + n0 + c);
        t[r][c] = v.x; t[r][c + 1] = v.y; t[r][c + 2] = v.z; t[r][c + 3] = v.w;
    }
    __syncthreads();
#pragma unroll
    for (int i = 0; i < 4; i++) {
        int idx = tid + i * 256;
        int n = idx >> 3, ks = (idx & 7) << 2;
        u32 p0 = packh2(t[ks][n],     t[ks + 1][n]);
        u32 p1 = packh2(t[ks + 2][n], t[ks + 3][n]);
        size_t off = (size_t)(n0 + n) * K + k0 + ks;
        *(u32*)(dst + off)     = p0;
        *(u32*)(dst + off + 2) = p1;
    }
}

// merged variant for the 4 HxH weights; zoff selects entry range
__global__ void __launch_bounds__(256)
wconv4(const float* __restrict__ wq, const float* __restrict__ wk,
       const float* __restrict__ wv, const float* __restrict__ wo,
       __half* __restrict__ oqkv, __half* __restrict__ owo, int zoff)
{
    __shared__ float t[32][132];
    int z = blockIdx.z + zoff, l = z >> 2, which = z & 3;
    const float* src = (which == 0 ? wq : which == 1 ? wk : which == 2 ? wv : wo)
                       + (size_t)l * Hn * Hn;
    __half* dst;
    size_t obase;
    if (which < 3) { dst = oqkv; obase = (size_t)l * QKVN * Hn + (size_t)which * 768 * Hn; }
    else           { dst = owo;  obase = (size_t)l * Hn * Hn; }
    const int n0 = blockIdx.x * 128, k0 = blockIdx.y * 32;
    const int tid = threadIdx.x;

#pragma unroll
    for (int i = 0; i < 4; i++) {
        int idx = tid + i * 256;
        int r = idx >> 5, c = (idx & 31) << 2;
        float4 v = *(const float4*)(src + (size_t)(k0 + r) * Hn + n0 + c);
        t[r][c] = v.x; t[r][c + 1] = v.y; t[r][c + 2] = v.z; t[r][c + 3] = v.w;
    }
    __syncthreads();
#pragma unroll
    for (int i = 0; i < 4; i++) {
        int idx = tid + i * 256;
        int n = idx >> 3, ks = (idx & 7) << 2;
        u32 p0 = packh2(t[ks][n],     t[ks + 1][n]);
        u32 p1 = packh2(t[ks + 2][n], t[ks + 3][n]);
        size_t off = obase + (size_t)(n0 + n) * Hn + k0 + ks;
        *(u32*)(dst + off)     = p0;
        *(u32*)(dst + off + 2) = p1;
    }
}

// embed + biaspack merged
__global__ void embed_bias(const int* __restrict__ tok, const float* __restrict__ emb,
                           const float* __restrict__ pos, float* __restrict__ x,
                           __half* __restrict__ xf,
                           const float* __restrict__ bq, const float* __restrict__ bk,
                           const float* __restrict__ bv, float* __restrict__ obias) {
    if (blockIdx.x < MR) {
        int row = blockIdx.x;
        int t = tok[row];
        const float* e = emb + (size_t)t * Hn;
        const float* p = pos + (size_t)(row % Sn) * Hn;
        size_t base = (size_t)row * Hn;
        for (int c = threadIdx.x; c < Hn; c += blockDim.x) {
            float v = e[c] + p[c];
            x[base + c] = v;
            xf[base + c] = __float2half(v);
        }
    } else {
        int i = (blockIdx.x - MR) * 256 + threadIdx.x;
        if (i < Ln * QKVN) {
            int l = i / QKVN, n = i - l * QKVN;
            float v = (n < 768) ? bq[l * Hn + n]
                    : (n < 1536) ? bk[l * Hn + n - 768] : bv[l * Hn + n - 1536];
            obias[i] = v;
        }
    }
}

// ==================================================================
// warp-per-row layernorm over (y0 + y1 + y2 + bias + resid)
// ==================================================================
__global__ void __launch_bounds__(256)
layernorm_sum(const float* __restrict__ y0, const float* __restrict__ bias,
              const float* __restrict__ resid,
              const float* __restrict__ g, const float* __restrict__ be,
              float* __restrict__ out, __half* __restrict__ of) {
    const int row = blockIdx.x * 8 + (threadIdx.x >> 5);
    const int lane = threadIdx.x & 31;
    const size_t rb = (size_t)row * Hn;
    const float* y1 = y0 + (size_t)MR * Hn;
    const float* y2 = y1 + (size_t)MR * Hn;

    float4 v[6];
    float s = 0.f, sq = 0.f;
#pragma unroll
    for (int i = 0; i < 6; i++) {
        int idx = i * 128 + lane * 4;
        float4 a0 = *(const float4*)(y0 + rb + idx);
        float4 a1 = *(const float4*)(y1 + rb + idx);
        float4 a2 = *(const float4*)(y2 + rb + idx);
        float4 bv = *(const float4*)(bias + idx);
        float4 rv = *(const float4*)(resid + rb + idx);
        v[i].x = a0.x + a1.x + a2.x + bv.x + rv.x;
        v[i].y = a0.y + a1.y + a2.y + bv.y + rv.y;
        v[i].z = a0.z + a1.z + a2.z + bv.z + rv.z;
        v[i].w = a0.w + a1.w + a2.w + bv.w + rv.w;
        s  += v[i].x + v[i].y + v[i].z + v[i].w;
        sq += v[i].x * v[i].x + v[i].y * v[i].y + v[i].z * v[i].z + v[i].w * v[i].w;
    }
#pragma unroll
    for (int o = 16; o; o >>= 1) {
        s  += __shfl_xor_sync(0xffffffffu, s, o);
        sq += __shfl_xor_sync(0xffffffffu, sq, o);
    }
    float m = s * (1.0f / Hn);
    float var = sq * (1.0f / Hn) - m * m;
    float inv = rsqrtf(var + 1e-12f);

#pragma unroll
    for (int i = 0; i < 6; i++) {
        int idx = i * 128 + lane * 4;
        float4 gg = *(const float4*)(g + idx);
        float4 bb = *(const float4*)(be + idx);
        float4 r;
        r.x = (v[i].x - m) * inv * gg.x + bb.x;
        r.y = (v[i].y - m) * inv * gg.y + bb.y;
        r.z = (v[i].z - m) * inv * gg.z + bb.z;
        r.w = (v[i].w - m) * inv * gg.w + bb.w;
        *(float4*)(out + rb + idx) = r;
        u32 h0 = packh2(r.x, r.y), h1 = packh2(r.z, r.w);
        *(u32*)(of + rb + idx)     = h0;
        *(u32*)(of + rb + idx + 2) = h1;
    }
}

// ==================================================================
#define SMEM_G1B (3 * (128*128 + 128*128))       // 98304 (128x128)
#define SMEM_G1A (3 * (64*128  + 128*128))       // 73728 (64x128)

extern "C" void kernel_launch(void* const* d_in, const int* in_sizes, int n_in,
                              void* d_out, int out_size) {
    const int*   tok = (const int*)d_in[0];
    const float* emb = (const float*)d_in[1];
    const float* pos = (const float*)d_in[2];
    const float* wq  = (const float*)d_in[3];
    const float* bq  = (const float*)d_in[4];
    const float* wk  = (const float*)d_in[5];
    const float* bk  = (const float*)d_in[6];
    const float* wv  = (const float*)d_in[7];
    const float* bv  = (const float*)d_in[8];
    const float* wo  = (const float*)d_in[9];
    const float* bo  = (const float*)d_in[10];
    const float* g1  = (const float*)d_in[11];
    const float* be1 = (const float*)d_in[12];
    const float* w1  = (const float*)d_in[13];
    const float* b1  = (const float*)d_in[14];
    const float* w2  = (const float*)d_in[15];
    const float* b2  = (const float*)d_in[16];
    const float* g2  = (const float*)d_in[17];
    const float* be2 = (const float*)d_in[18];

    float* out      = (float*)d_out;
    float* attn_out = out + (size_t)MR * Hn;

    float *x, *y, *bqkv;
    __half *wqkv16, *wo16, *w116, *w216, *xf, *qkv16, *ct, *f16;
    cudaGetSymbolAddress((void**)&x, g_x);
    cudaGetSymbolAddress((void**)&y, g_y);
    cudaGetSymbolAddress((void**)&bqkv, g_bqkv);
    cudaGetSymbolAddress((void**)&wqkv16, g_wqkv16);
    cudaGetSymbolAddress((void**)&wo16, g_wo16);
    cudaGetSymbolAddress((void**)&w116, g_w116);
    cudaGetSymbolAddress((void**)&w216, g_w216);
    cudaGetSymbolAddress((void**)&xf, g_xf);
    cudaGetSymbolAddress((void**)&qkv16, g_qkv16);
    cudaGetSymbolAddress((void**)&ct, g_ct16);
    cudaGetSymbolAddress((void**)&f16, g_f16);

    cudaFuncSetAttribute(gemm1<128,128,0>, cudaFuncAttributeMaxDynamicSharedMemorySize, SMEM_G1B);
    cudaFuncSetAttribute(gemm1<64,128,5>,  cudaFuncAttributeMaxDynamicSharedMemorySize, SMEM_G1A);
    cudaFuncSetAttribute(gemm1<128,128,4>, cudaFuncAttributeMaxDynamicSharedMemorySize, SMEM_G1B);
    cudaFuncSetAttribute(attn_fused, cudaFuncAttributeMaxDynamicSharedMemorySize, SMEM_ATT);

    static cudaStream_t s2 = nullptr;
    static cudaEvent_t ev1 = nullptr, ev2 = nullptr;
    if (!s2) {
        cudaStreamCreateWithFlags(&s2, cudaStreamNonBlocking);
        cudaEventCreateWithFlags(&ev1, cudaEventDisableTiming);
        cudaEventCreateWithFlags(&ev2, cudaEventDisableTiming);
    }

    // ---- critical-path prologue: ONLY wq/wk/wv of layer 0 + embed ----
    wconv4<<<dim3(Hn/128, Hn/32, 3), 256>>>(wq, wk, wv, wo, wqkv16, wo16, 0);
    embed_bias<<<MR + (Ln*QKVN + 255)/256, 256>>>(tok, emb, pos, x, xf, bq, bk, bv, bqkv);

    // ---- side stream: everything else ----
    cudaEventRecord(ev1, 0);
    cudaStreamWaitEvent(s2, ev1, 0);
    wconv4<<<dim3(Hn/128, Hn/32, 4*Ln - 3), 256, 0, s2>>>(wq, wk, wv, wo, wqkv16, wo16, 3);
    wconv<<<dim3(Fn/128, Hn/32, Ln), 256, 0, s2>>>(w1, w116, Hn, Fn, (long)Hn*Fn, (long)Hn*Fn);
    wconv<<<dim3(Hn/128, Fn/32, Ln), 256, 0, s2>>>(w2, w216, Fn, Hn, (long)Fn*Hn, (long)Fn*Hn);
    cudaEventRecord(ev2, s2);

    for (int l = 0; l < Ln; l++) {
        float* attnL = attn_out + (size_t)l * BH * Sn * Sn;
        bool last = (l == Ln - 1);
        float* lnout = last ? out : x;

        // fused QKV projection (fp16)
        gemm1<128,128,0><<<dim3(QKVN/128, MR/128), 512, SMEM_G1B>>>(
            xf, Hn, wqkv16 + (size_t)l * QKVN * Hn, Hn, nullptr, qkv16, QKVN,
            bqkv + (size_t)l * QKVN, Hn);

        // scores + softmax + P@V
        attn_fused<<<dim3(Sn/64, BH), 256, SMEM_ATT>>>(qkv16, tok, attnL, ct);

        if (l == 0) cudaStreamWaitEvent(0, ev2, 0);   // remaining weights ready

        // Wo split-K=3 -> fp32 partials (576 CTAs, 97% wave util)
        gemm1<64,128,5><<<dim3(Hn/128, MR/64, 3), 512, SMEM_G1A>>>(
            ct, Hn, wo16 + (size_t)l * Hn * Hn, Hn, y, nullptr, Hn, nullptr, Hn);
        layernorm_sum<<<MR/8, 256>>>(y, bo + (size_t)l * Hn, x,
                                     g1 + (size_t)l * Hn, be1 + (size_t)l * Hn, x, xf);

        // FFN1 (relu)
        gemm1<128,128,4><<<dim3(Fn/128, MR/128), 512, SMEM_G1B>>>(
            xf, Hn, w116 + (size_t)l * Hn * Fn, Hn, nullptr, f16, Fn,
            b1 + (size_t)l * Fn, Hn);

        // FFN2 split-K=3 -> fp32 partials
        gemm1<64,128,5><<<dim3(Hn/128, MR/64, 3), 512, SMEM_G1A>>>(
            f16, Fn, w216 + (size_t)l * Fn * Hn, Fn, y, nullptr, Hn, nullptr, Fn);
        layernorm_sum<<<MR/8, 256>>>(y, b2 + (size_t)l * Hn, x,
                                     g2 + (size_t)l * Hn, be2 + (size_t)l * Hn, lnout, xf);
    }
}

// round 15
// speedup vs baseline: 1.0800x; 1.0080x over previous
#include <cuda_runtime.h>
#include <cuda_bf16.h>
#include <cuda_fp16.h>

typedef unsigned int u32;
typedef unsigned long long u64;

#define Bn 4
#define Sn 512
#define Hn 768
#define NHn 12
#define Fn 3072
#define Ln 6
#define MR (Bn*Sn)          // 2048
#define QKVN 2304
#define BH (Bn*NHn)         // 48

// ---------------- scratch (device globals) ----------------
__device__ __half g_wqkv16[(size_t)Ln*QKVN*Hn];
__device__ __half g_wo16[(size_t)Ln*Hn*Hn];
__device__ __half g_w116[(size_t)Ln*Hn*Fn];
__device__ __half g_w216[(size_t)Ln*Fn*Hn];
__device__ float g_x[MR*Hn];
__device__ float g_y[3*MR*Hn];                 // split-K partials (fp32, 3-way)
__device__ float g_bqkv[Ln*QKVN];
__device__ __half g_xf[MR*Hn];
__device__ __half g_qkv16[(size_t)MR*QKVN];
__device__ __half g_ct16[MR*Hn];
__device__ __half g_f16[(size_t)MR*Fn];

// ---------------- helpers ----------------
__device__ __forceinline__ u32 s2u(const void* p) {
    u32 a;
    asm("{ .reg .u64 t; cvta.to.shared.u64 t, %1; cvt.u32.u64 %0, t; }" : "=r"(a) : "l"(p));
    return a;
}
__device__ __forceinline__ u32 swz(u32 o) { return o ^ ((o >> 3) & 0x70); }

__device__ __forceinline__ void cpasync16(u32 dst, const void* src) {
    asm volatile("cp.async.cg.shared.global [%0], [%1], 16;" :: "r"(dst), "l"(src) : "memory");
}
__device__ __forceinline__ void ldsm4(u32& r0, u32& r1, u32& r2, u32& r3, u32 a) {
    asm volatile("ldmatrix.sync.aligned.m8n8.x4.shared.b16 {%0,%1,%2,%3}, [%4];"
                 : "=r"(r0), "=r"(r1), "=r"(r2), "=r"(r3) : "r"(a));
}
__device__ __forceinline__ void ldsm4t(u32& r0, u32& r1, u32& r2, u32& r3, u32 a) {
    asm volatile("ldmatrix.sync.aligned.m8n8.x4.trans.shared.b16 {%0,%1,%2,%3}, [%4];"
                 : "=r"(r0), "=r"(r1), "=r"(r2), "=r"(r3) : "r"(a));
}
__device__ __forceinline__ void mma16816h(float* c, const u32* a, const u32* b) {
    asm volatile("mma.sync.aligned.m16n8k16.row.col.f32.f16.f16.f32 "
                 "{%0,%1,%2,%3}, {%4,%5,%6,%7}, {%8,%9}, {%0,%1,%2,%3};"
                 : "+f"(c[0]), "+f"(c[1]), "+f"(c[2]), "+f"(c[3])
                 : "r"(a[0]), "r"(a[1]), "r"(a[2]), "r"(a[3]), "r"(b[0]), "r"(b[1]));
}
__device__ __forceinline__ u32 packh2(float v0, float v1) {
    __half2 h = __floats2half2_rn(v0, v1);
    return *reinterpret_cast<u32*>(&h);
}
__device__ __forceinline__ u32 ex2h2(u32 t) {
    u32 o;
    asm("ex2.approx.f16x2 %0, %1;" : "=r"(o) : "r"(t));
    return o;
}

// ==================================================================
// fp16 single-pass GEMM. MT x NT, BK=64, 512 threads (16 warps 4x4).
// EPI: 0=bias->fp16  4=bias+relu->fp16  5=split-K/3 raw partial -> fp32
// ==================================================================
template<int MT, int NT, int EPI>
__global__ void __launch_bounds__(512)
gemm1(const __half* __restrict__ A, int lda, const __half* __restrict__ B, int ldb,
      float* __restrict__ Cf, __half* __restrict__ Ch, int ldc,
      const float* __restrict__ bias, int K)
{
    constexpr int WM = MT / 4, WN = NT / 4;
    constexpr int MI = WM / 16, NI = WN / 8;
    constexpr u32 ASZ = (u32)MT * 128u, BSZ = (u32)NT * 128u;
    constexpr u32 STG = ASZ + BSZ;

    if (EPI == 5) {
        int ks = K / 3;
        A += (size_t)blockIdx.z * (u32)ks;
        B += (size_t)blockIdx.z * (u32)ks;
        K = ks;
    }

    extern __shared__ char smem[];
    const u32 sb = s2u(smem);
    const int tid = threadIdx.x, wid = tid >> 5, lane = tid & 31;
    const int warp_m = wid >> 2, warp_n = wid & 3;
    const int m0 = blockIdx.y * MT, n0 = blockIdx.x * NT;
    const int nsl = K >> 6;

    float acc[MI][NI][4];
#pragma unroll
    for (int mi = 0; mi < MI; mi++)
#pragma unroll
        for (int ni = 0; ni < NI; ni++)
#pragma unroll
            for (int q = 0; q < 4; q++) acc[mi][ni][q] = 0.f;

    auto prefetch = [&](int sl) {
        const u32 base = sb + (u32)(sl % 3) * STG;
#pragma unroll
        for (int i = 0; i < MT * 8 / 512; i++) {
            int u = tid + i * 512;
            int r = u >> 3, c = u & 7;
            cpasync16(base + swz((u32)(r * 128 + c * 16)),
                      A + (size_t)(m0 + r) * lda + sl * 64 + c * 8);
        }
#pragma unroll
        for (int i = 0; i < NT * 8 / 512; i++) {
            int u = tid + i * 512;
            int r = u >> 3, c = u & 7;
            cpasync16(base + ASZ + swz((u32)(r * 128 + c * 16)),
                      B + (size_t)(n0 + r) * ldb + sl * 64 + c * 8);
        }
        asm volatile("cp.async.commit_group;" ::: "memory");
    };

    prefetch(0); prefetch(1);

    for (int it = 0; it < nsl; it++) {
        if (it < nsl - 1) asm volatile("cp.async.wait_group 1;" ::: "memory");
        else              asm volatile("cp.async.wait_group 0;" ::: "memory");
        __syncthreads();
        if (it + 2 < nsl) prefetch(it + 2);

        const u32 ab = sb + (u32)(it % 3) * STG;
        const u32 bb = ab + ASZ;

#pragma unroll
        for (int ks = 0; ks < 4; ks++) {
            u32 ar[MI][4];
#pragma unroll
            for (int mi = 0; mi < MI; mi++) {
                int row = warp_m * WM + mi * 16 + (lane & 15);
                u32 off = swz((u32)(row * 128 + (ks * 16 + (lane >> 4) * 8) * 2));
                ldsm4(ar[mi][0], ar[mi][1], ar[mi][2], ar[mi][3], ab + off);
            }
            u32 br[NI][2];
#pragma unroll
            for (int nj = 0; nj < NI / 2; nj++) {
                int nrow = warp_n * WN + nj * 16 + (lane & 7) + ((lane >> 4) << 3);
                u32 off = swz((u32)(nrow * 128 + (ks * 16 + ((lane >> 3) & 1) * 8) * 2));
                u32 r0, r1, r2, r3;
                ldsm4(r0, r1, r2, r3, bb + off);
                br[2 * nj][0] = r0; br[2 * nj][1] = r1;
                br[2 * nj + 1][0] = r2; br[2 * nj + 1][1] = r3;
            }
#pragma unroll
            for (int mi = 0; mi < MI; mi++)
#pragma unroll
                for (int ni = 0; ni < NI; ni++)
                    mma16816h(acc[mi][ni], ar[mi], br[ni]);
        }
    }

    const int tg = lane & 3, g = lane >> 2;
    const size_t zoff = (EPI == 5) ? (size_t)blockIdx.z * MR * ldc : 0;
#pragma unroll
    for (int mi = 0; mi < MI; mi++)
#pragma unroll
        for (int half = 0; half < 2; half++) {
            const int mrow = m0 + warp_m * WM + mi * 16 + half * 8 + g;
#pragma unroll
            for (int ni = 0; ni < NI; ni++) {
                const int col = n0 + warp_n * WN + ni * 8 + tg * 2;
                float v0 = acc[mi][ni][half * 2];
                float v1 = acc[mi][ni][half * 2 + 1];
                size_t off = (size_t)mrow * ldc + col;
                if (EPI == 5) {
                    *(float2*)(Cf + zoff + off) = make_float2(v0, v1);
                } else {
                    v0 += bias[col]; v1 += bias[col + 1];
                    if (EPI == 4) { v0 = fmaxf(v0, 0.f); v1 = fmaxf(v1, 0.f); }
                    *(u32*)(Ch + off) = packh2(v0, v1);
                }
            }
        }
}

// ==================================================================
// Fused attention (all fp16): scores + softmax + P@V. 64 q-rows/(b,h).
// exp via ex2.approx.f16x2 (2 exps/MUFU op); row sums in fp32.
// smem: Q[0,8K)  K[8K,72K)->P  V[72K,136K)  red[136K..]
// ==================================================================
#define ATT_KP   8192u
#define ATT_V    73728u
#define ATT_RED  139264
#define SMEM_ATT (ATT_RED + 2048)
#define SCL_LOG2E 0.18033688f   /* 0.125 * log2(e) */

__global__ void __launch_bounds__(256)
attn_fused(const __half* __restrict__ qkv, const int* __restrict__ tok,
           float* __restrict__ attn, __half* __restrict__ ct)
{
    extern __shared__ char smem[];
    const u32 sb = s2u(smem);
    const int tid = threadIdx.x, wid = tid >> 5, lane = tid & 31;
    const int g = lane >> 2, tg = lane & 3;
    const int m0 = blockIdx.x * 64;
    const int zbh = blockIdx.y;
    const int b = zbh / NHn, h = zbh - b * NHn;

    const __half* Q_src = qkv + (size_t)(b * Sn + m0) * QKVN + h * 64;
    const __half* K_src = qkv + (size_t)(b * Sn) * QKVN + 768 + h * 64;
    const __half* V_src = qkv + (size_t)(b * Sn) * QKVN + 1536 + h * 64;

    for (int u = tid; u < 512; u += 256) {
        int r = u >> 3, c = u & 7;
        cpasync16(sb + swz((u32)(r * 128 + c * 16)), Q_src + (size_t)r * QKVN + c * 8);
    }
    for (int u = tid; u < 4096; u += 256) {
        int r = u >> 3, c = u & 7;
        cpasync16(sb + ATT_KP + swz((u32)(r * 128 + c * 16)), K_src + (size_t)r * QKVN + c * 8);
    }
    asm volatile("cp.async.commit_group;" ::: "memory");
    for (int u = tid; u < 4096; u += 256) {
        int r = u >> 3, c = u & 7;
        cpasync16(sb + ATT_V + swz((u32)(r * 128 + c * 16)), V_src + (size_t)r * QKVN + c * 8);
    }
    asm volatile("cp.async.commit_group;" ::: "memory");

    asm volatile("cp.async.wait_group 1;" ::: "memory");
    __syncthreads();

    // ---- scores = Q K^T ----
    float acc[4][8][4];
#pragma unroll
    for (int mi = 0; mi < 4; mi++)
#pragma unroll
        for (int ni = 0; ni < 8; ni++)
#pragma unroll
            for (int q = 0; q < 4; q++) acc[mi][ni][q] = 0.f;

#pragma unroll
    for (int ks = 0; ks < 4; ks++) {
        u32 arg[4][4];
#pragma unroll
        for (int mi = 0; mi < 4; mi++) {
            int row = mi * 16 + (lane & 15);
            u32 off = swz((u32)(row * 128 + (ks * 16 + (lane >> 4) * 8) * 2));
            ldsm4(arg[mi][0], arg[mi][1], arg[mi][2], arg[mi][3], sb + off);
        }
        u32 brg[8][2];
#pragma unroll
        for (int nj = 0; nj < 4; nj++) {
            int nrow = wid * 64 + nj * 16 + (lane & 7) + ((lane >> 4) << 3);
            u32 off = swz((u32)(nrow * 128 + (ks * 16 + ((lane >> 3) & 1) * 8) * 2));
            u32 r0, r1, r2, r3;
            ldsm4(r0, r1, r2, r3, sb + ATT_KP + off);
            brg[2 * nj][0] = r0; brg[2 * nj][1] = r1;
            brg[2 * nj + 1][0] = r2; brg[2 * nj + 1][1] = r3;
        }
#pragma unroll
        for (int mi = 0; mi < 4; mi++)
#pragma unroll
            for (int ni = 0; ni < 8; ni++)
                mma16816h(acc[mi][ni], arg[mi], brg[ni]);
    }
    __syncthreads();

    // ---- scale + mask (log2 space) + exp in fp16x2 ----
    float mkl[8][2];
#pragma unroll
    for (int ni = 0; ni < 8; ni++) {
        int c = wid * 64 + ni * 8 + tg * 2;
        mkl[ni][0] = (tok[b * Sn + c]     == 0) ? -30000.f : 0.f;
        mkl[ni][1] = (tok[b * Sn + c + 1] == 0) ? -30000.f : 0.f;
    }

    float* red = (float*)(smem + ATT_RED);
    u32 e[4][8][2];      // exp values as half2 pairs
    float rsum[8];

#pragma unroll
    for (int mi = 0; mi < 4; mi++)
#pragma unroll
        for (int half = 0; half < 2; half++) {
            float s = 0.f;
#pragma unroll
            for (int ni = 0; ni < 8; ni++) {
                float t0 = fmaf(acc[mi][ni][half * 2],     SCL_LOG2E, mkl[ni][0]);
                float t1 = fmaf(acc[mi][ni][half * 2 + 1], SCL_LOG2E, mkl[ni][1]);
                u32 ev = ex2h2(packh2(t0, t1));
                e[mi][ni][half] = ev;
                float2 f = __half22float2(*(__half2*)&ev);
                s += f.x + f.y;
            }
            s += __shfl_xor_sync(0xffffffffu, s, 1);
            s += __shfl_xor_sync(0xffffffffu, s, 2);
            int row = mi * 16 + half * 8 + g;
            if (tg == 0) red[row * 8 + wid] = s;
        }
    __syncthreads();
#pragma unroll
    for (int mi = 0; mi < 4; mi++)
#pragma unroll
        for (int half = 0; half < 2; half++) {
            int row = mi * 16 + half * 8 + g;
            float s = 0.f;
#pragma unroll
            for (int w = 0; w < 8; w++) s += red[row * 8 + w];
            rsum[mi * 2 + half] = 1.f / s;
        }

    // ---- write attn fp32 + P fp16 into smem (8 slabs 64x64 over K) ----
#pragma unroll
    for (int mi = 0; mi < 4; mi++)
#pragma unroll
        for (int half = 0; half < 2; half++) {
            int row = mi * 16 + half * 8 + g;
            size_t rbase = (size_t)zbh * Sn * Sn + (size_t)(m0 + row) * Sn;
            float inv = rsum[mi * 2 + half];
            __half2 hinv = __floats2half2_rn(inv, inv);
#pragma unroll
            for (int ni = 0; ni < 8; ni++) {
                int col = ni * 8 + tg * 2;
                u32 ev = e[mi][ni][half];
                __half2 eh = *(__half2*)&ev;
                float2 f = __half22float2(eh);
                *(float2*)(attn + rbase + wid * 64 + col) =
                    make_float2(f.x * inv, f.y * inv);
                __half2 p = __hmul2(eh, hinv);
                u32 off = (u32)(wid * 8192) + swz((u32)(row * 128 + col * 2));
                *(u32*)(smem + ATT_KP + off) = *(u32*)&p;
            }
        }

    asm volatile("cp.async.wait_group 0;" ::: "memory");
    __syncthreads();

    // ---- ctx = P @ V (V via trans-ldmatrix) ----
    const int wm = wid >> 2, wn = wid & 3;
    float acc2[2][2][4];
#pragma unroll
    for (int mi = 0; mi < 2; mi++)
#pragma unroll
        for (int ni = 0; ni < 2; ni++)
#pragma unroll
            for (int q = 0; q < 4; q++) acc2[mi][ni][q] = 0.f;

#pragma unroll 2
    for (int sl = 0; sl < 8; sl++) {
#pragma unroll
        for (int ks = 0; ks < 4; ks++) {
            u32 ar[2][4];
#pragma unroll
            for (int mi = 0; mi < 2; mi++) {
                int row = wm * 32 + mi * 16 + (lane & 15);
                u32 aoff = (u32)(sl * 8192) + swz((u32)(row * 128 + (ks * 16 + (lane >> 4) * 8) * 2));
                ldsm4(ar[mi][0], ar[mi][1], ar[mi][2], ar[mi][3], sb + ATT_KP + aoff);
            }
            int srow = sl * 64 + ks * 16 + (lane & 7) + ((lane >> 3) & 1) * 8;
            int dcol = wn * 16 + ((lane >> 4) << 3);
            u32 boff = swz((u32)(srow * 128 + dcol * 2));
            u32 br[2][2], r0, r1, r2, r3;
            ldsm4t(r0, r1, r2, r3, sb + ATT_V + boff);
            br[0][0] = r0; br[0][1] = r1; br[1][0] = r2; br[1][1] = r3;
#pragma unroll
            for (int mi = 0; mi < 2; mi++)
#pragma unroll
                for (int ni = 0; ni < 2; ni++)
                    mma16816h(acc2[mi][ni], ar[mi], br[ni]);
        }
    }

#pragma unroll
    for (int mi = 0; mi < 2; mi++)
#pragma unroll
        for (int half = 0; half < 2; half++) {
            int row = m0 + wm * 32 + mi * 16 + half * 8 + g;
#pragma unroll
            for (int ni = 0; ni < 2; ni++) {
                int col = wn * 16 + ni * 8 + tg * 2;
                size_t off = (size_t)(b * Sn + row) * Hn + h * 64 + col;
                *(u32*)(ct + off) = packh2(acc2[mi][ni][half * 2], acc2[mi][ni][half * 2 + 1]);
            }
        }
}

// ==================================================================
// weight convert+transpose: fp32 [K,N] -> fp16 [N,K]
// ==================================================================
__global__ void __launch_bounds__(256)
wconv(const float* __restrict__ src0, __half* __restrict__ dst0,
      int K, int N, long in_l, long out_l)
{
    __shared__ float t[32][132];
    const float* src = src0 + (size_t)blockIdx.z * in_l;
    __half* dst = dst0 + (size_t)blockIdx.z * out_l;
    const int n0 = blockIdx.x * 128, k0 = blockIdx.y * 32;
    const int tid = threadIdx.x;

#pragma unroll
    for (int i = 0; i < 4; i++) {
        int idx = tid + i * 256;
        int r = idx >> 5, c = (idx & 31) << 2;
        float4 v = *(const float4*)(src + (size_t)(k0 + r) * N + n0 + c);
        t[r][c] = v.x; t[r][c + 1] = v.y; t[r][c + 2] = v.z; t[r][c + 3] = v.w;
    }
    __syncthreads();
#pragma unroll
    for (int i = 0; i < 4; i++) {
        int idx = tid + i * 256;
        int n = idx >> 3, ks = (idx & 7) << 2;
        u32 p0 = packh2(t[ks][n],     t[ks + 1][n]);
        u32 p1 = packh2(t[ks + 2][n], t[ks + 3][n]);
        size_t off = (size_t)(n0 + n) * K + k0 + ks;
        *(u32*)(dst + off)     = p0;
        *(u32*)(dst + off + 2) = p1;
    }
}

// merged variant for the 4 HxH weights; zoff selects entry range
__global__ void __launch_bounds__(256)
wconv4(const float* __restrict__ wq, const float* __restrict__ wk,
       const float* __restrict__ wv, const float* __restrict__ wo,
       __half* __restrict__ oqkv, __half* __restrict__ owo, int zoff)
{
    __shared__ float t[32][132];
    int z = blockIdx.z + zoff, l = z >> 2, which = z & 3;
    const float* src = (which == 0 ? wq : which == 1 ? wk : which == 2 ? wv : wo)
                       + (size_t)l * Hn * Hn;
    __half* dst;
    size_t obase;
    if (which < 3) { dst = oqkv; obase = (size_t)l * QKVN * Hn + (size_t)which * 768 * Hn; }
    else           { dst = owo;  obase = (size_t)l * Hn * Hn; }
    const int n0 = blockIdx.x * 128, k0 = blockIdx.y * 32;
    const int tid = threadIdx.x;

#pragma unroll
    for (int i = 0; i < 4; i++) {
        int idx = tid + i * 256;
        int r = idx >> 5, c = (idx & 31) << 2;
        float4 v = *(const float4*)(src + (size_t)(k0 + r) * Hn + n0 + c);
        t[r][c] = v.x; t[r][c + 1] = v.y; t[r][c + 2] = v.z; t[r][c + 3] = v.w;
    }
    __syncthreads();
#pragma unroll
    for (int i = 0; i < 4; i++) {
        int idx = tid + i * 256;
        int n = idx >> 3, ks = (idx & 7) << 2;
        u32 p0 = packh2(t[ks][n],     t[ks + 1][n]);
        u32 p1 = packh2(t[ks + 2][n], t[ks + 3][n]);
        size_t off = obase + (size_t)(n0 + n) * Hn + k0 + ks;
        *(u32*)(dst + off)     = p0;
        *(u32*)(dst + off + 2) = p1;
    }
}

// embed + biaspack merged
__global__ void embed_bias(const int* __restrict__ tok, const float* __restrict__ emb,
                           const float* __restrict__ pos, float* __restrict__ x,
                           __half* __restrict__ xf,
                           const float* __restrict__ bq, const float* __restrict__ bk,
                           const float* __restrict__ bv, float* __restrict__ obias) {
    if (blockIdx.x < MR) {
        int row = blockIdx.x;
        int t = tok[row];
        const float* e = emb + (size_t)t * Hn;
        const float* p = pos + (size_t)(row % Sn) * Hn;
        size_t base = (size_t)row * Hn;
        for (int c = threadIdx.x; c < Hn; c += blockDim.x) {
            float v = e[c] + p[c];
            x[base + c] = v;
            xf[base + c] = __float2half(v);
        }
    } else {
        int i = (blockIdx.x - MR) * 256 + threadIdx.x;
        if (i < Ln * QKVN) {
            int l = i / QKVN, n = i - l * QKVN;
            float v = (n < 768) ? bq[l * Hn + n]
                    : (n < 1536) ? bk[l * Hn + n - 768] : bv[l * Hn + n - 1536];
            obias[i] = v;
        }
    }
}

// ==================================================================
// warp-per-row layernorm over (y0 + y1 + y2 + bias + resid)
// ==================================================================
__global__ void __launch_bounds__(256)
layernorm_sum(const float* __restrict__ y0, const float* __restrict__ bias,
              const float* __restrict__ resid,
              const float* __restrict__ g, const float* __restrict__ be,
              float* __restrict__ out, __half* __restrict__ of) {
    const int row = blockIdx.x * 8 + (threadIdx.x >> 5);
    const int lane = threadIdx.x & 31;
    const size_t rb = (size_t)row * Hn;
    const float* y1 = y0 + (size_t)MR * Hn;
    const float* y2 = y1 + (size_t)MR * Hn;

    float4 v[6];
    float s = 0.f, sq = 0.f;
#pragma unroll
    for (int i = 0; i < 6; i++) {
        int idx = i * 128 + lane * 4;
        float4 a0 = *(const float4*)(y0 + rb + idx);
        float4 a1 = *(const float4*)(y1 + rb + idx);
        float4 a2 = *(const float4*)(y2 + rb + idx);
        float4 bv = *(const float4*)(bias + idx);
        float4 rv = *(const float4*)(resid + rb + idx);
        v[i].x = a0.x + a1.x + a2.x + bv.x + rv.x;
        v[i].y = a0.y + a1.y + a2.y + bv.y + rv.y;
        v[i].z = a0.z + a1.z + a2.z + bv.z + rv.z;
        v[i].w = a0.w + a1.w + a2.w + bv.w + rv.w;
        s  += v[i].x + v[i].y + v[i].z + v[i].w;
        sq += v[i].x * v[i].x + v[i].y * v[i].y + v[i].z * v[i].z + v[i].w * v[i].w;
    }
#pragma unroll
    for (int o = 16; o; o >>= 1) {
        s  += __shfl_xor_sync(0xffffffffu, s, o);
        sq += __shfl_xor_sync(0xffffffffu, sq, o);
    }
    float m = s * (1.0f / Hn);
    float var = sq * (1.0f / Hn) - m * m;
    float inv = rsqrtf(var + 1e-12f);

#pragma unroll
    for (int i = 0; i < 6; i++) {
        int idx = i * 128 + lane * 4;
        float4 gg = *(const float4*)(g + idx);
        float4 bb = *(const float4*)(be + idx);
        float4 r;
        r.x = (v[i].x - m) * inv * gg.x + bb.x;
        r.y = (v[i].y - m) * inv * gg.y + bb.y;
        r.z = (v[i].z - m) * inv * gg.z + bb.z;
        r.w = (v[i].w - m) * inv * gg.w + bb.w;
        *(float4*)(out + rb + idx) = r;
        u32 h0 = packh2(r.x, r.y), h1 = packh2(r.z, r.w);
        *(u32*)(of + rb + idx)     = h0;
        *(u32*)(of + rb + idx + 2) = h1;
    }
}

// ==================================================================
#define SMEM_G1B (3 * (128*128 + 128*128))       // 98304 (128x128)
#define SMEM_G1A (3 * (64*128  + 128*128))       // 73728 (64x128)

extern "C" void kernel_launch(void* const* d_in, const int* in_sizes, int n_in,
                              void* d_out, int out_size) {
    const int*   tok = (const int*)d_in[0];
    const float* emb = (const float*)d_in[1];
    const float* pos = (const float*)d_in[2];
    const float* wq  = (const float*)d_in[3];
    const float* bq  = (const float*)d_in[4];
    const float* wk  = (const float*)d_in[5];
    const float* bk  = (const float*)d_in[6];
    const float* wv  = (const float*)d_in[7];
    const float* bv  = (const float*)d_in[8];
    const float* wo  = (const float*)d_in[9];
    const float* bo  = (const float*)d_in[10];
    const float* g1  = (const float*)d_in[11];
    const float* be1 = (const float*)d_in[12];
    const float* w1  = (const float*)d_in[13];
    const float* b1  = (const float*)d_in[14];
    const float* w2  = (const float*)d_in[15];
    const float* b2  = (const float*)d_in[16];
    const float* g2  = (const float*)d_in[17];
    const float* be2 = (const float*)d_in[18];

    float* out      = (float*)d_out;
    float* attn_out = out + (size_t)MR * Hn;

    float *x, *y, *bqkv;
    __half *wqkv16, *wo16, *w116, *w216, *xf, *qkv16, *ct, *f16;
    cudaGetSymbolAddress((void**)&x, g_x);
    cudaGetSymbolAddress((void**)&y, g_y);
    cudaGetSymbolAddress((void**)&bqkv, g_bqkv);
    cudaGetSymbolAddress((void**)&wqkv16, g_wqkv16);
    cudaGetSymbolAddress((void**)&wo16, g_wo16);
    cudaGetSymbolAddress((void**)&w116, g_w116);
    cudaGetSymbolAddress((void**)&w216, g_w216);
    cudaGetSymbolAddress((void**)&xf, g_xf);
    cudaGetSymbolAddress((void**)&qkv16, g_qkv16);
    cudaGetSymbolAddress((void**)&ct, g_ct16);
    cudaGetSymbolAddress((void**)&f16, g_f16);

    cudaFuncSetAttribute(gemm1<128,128,0>, cudaFuncAttributeMaxDynamicSharedMemorySize, SMEM_G1B);
    cudaFuncSetAttribute(gemm1<64,128,5>,  cudaFuncAttributeMaxDynamicSharedMemorySize, SMEM_G1A);
    cudaFuncSetAttribute(gemm1<128,128,4>, cudaFuncAttributeMaxDynamicSharedMemorySize, SMEM_G1B);
    cudaFuncSetAttribute(attn_fused, cudaFuncAttributeMaxDynamicSharedMemorySize, SMEM_ATT);

    static cudaStream_t s2 = nullptr;
    static cudaEvent_t ev1 = nullptr, ev2 = nullptr;
    if (!s2) {
        cudaStreamCreateWithFlags(&s2, cudaStreamNonBlocking);
        cudaEventCreateWithFlags(&ev1, cudaEventDisableTiming);
        cudaEventCreateWithFlags(&ev2, cudaEventDisableTiming);
    }

    // ---- critical-path prologue: ONLY wq/wk/wv of layer 0 + embed ----
    wconv4<<<dim3(Hn/128, Hn/32, 3), 256>>>(wq, wk, wv, wo, wqkv16, wo16, 0);
    embed_bias<<<MR + (Ln*QKVN + 255)/256, 256>>>(tok, emb, pos, x, xf, bq, bk, bv, bqkv);

    // ---- side stream: everything else ----
    cudaEventRecord(ev1, 0);
    cudaStreamWaitEvent(s2, ev1, 0);
    wconv4<<<dim3(Hn/128, Hn/32, 4*Ln - 3), 256, 0, s2>>>(wq, wk, wv, wo, wqkv16, wo16, 3);
    wconv<<<dim3(Fn/128, Hn/32, Ln), 256, 0, s2>>>(w1, w116, Hn, Fn, (long)Hn*Fn, (long)Hn*Fn);
    wconv<<<dim3(Hn/128, Fn/32, Ln), 256, 0, s2>>>(w2, w216, Fn, Hn, (long)Fn*Hn, (long)Fn*Hn);
    cudaEventRecord(ev2, s2);

    for (int l = 0; l < Ln; l++) {
        float* attnL = attn_out + (size_t)l * BH * Sn * Sn;
        bool last = (l == Ln - 1);
        float* lnout = last ? out : x;

        // fused QKV projection (fp16)
        gemm1<128,128,0><<<dim3(QKVN/128, MR/128), 512, SMEM_G1B>>>(
            xf, Hn, wqkv16 + (size_t)l * QKVN * Hn, Hn, nullptr, qkv16, QKVN,
            bqkv + (size_t)l * QKVN, Hn);

        // scores + softmax + P@V
        attn_fused<<<dim3(Sn/64, BH), 256, SMEM_ATT>>>(qkv16, tok, attnL, ct);

        if (l == 0) cudaStreamWaitEvent(0, ev2, 0);   // remaining weights ready

        // Wo split-K=3 -> fp32 partials
        gemm1<64,128,5><<<dim3(Hn/128, MR/64, 3), 512, SMEM_G1A>>>(
            ct, Hn, wo16 + (size_t)l * Hn * Hn, Hn, y, nullptr, Hn, nullptr, Hn);
        layernorm_sum<<<MR/8, 256>>>(y, bo + (size_t)l * Hn, x,
                                     g1 + (size_t)l * Hn, be1 + (size_t)l * Hn, x, xf);

        // FFN1 (relu)
        gemm1<128,128,4><<<dim3(Fn/128, MR/128), 512, SMEM_G1B>>>(
            xf, Hn, w116 + (size_t)l * Hn * Fn, Hn, nullptr, f16, Fn,
            b1 + (size_t)l * Fn, Hn);

        // FFN2 split-K=3 -> fp32 partials
        gemm1<64,128,5><<<dim3(Hn/128, MR/64, 3), 512, SMEM_G1A>>>(
            f16, Fn, w216 + (size_t)l * Fn * Hn, Fn, y, nullptr, Hn, nullptr, Fn);
        layernorm_sum<<<MR/8, 256>>>(y, b2 + (size_t)l * Hn, x,
                                     g2 + (size_t)l * Hn, be2 + (size_t)l * Hn, lnout, xf);
    }
}